// round 6
// baseline (speedup 1.0000x reference)
#include <cuda_runtime.h>
#include <math.h>
#include <stdint.h>

// Problem constants (B=4, T=2048, C=1024, H=16, D=64)
#define Bn   4
#define Tn   2048
#define Cc   1024
#define NH   16
#define HD   64
#define MTOT (Bn * Tn)          // 8192 rows

// Scratch (device globals: allocation is forbidden)
__device__ float g_qkv[(size_t)MTOT * 3 * Cc];  // (B*T, 3C), tf32-rounded
__device__ float g_att[(size_t)MTOT * Cc];      // (B*T, C),  tf32-rounded
__device__ float g_xr [(size_t)MTOT * Cc];      // x rounded
__device__ float g_war[(size_t)3 * Cc * Cc];    // w_attn rounded
__device__ float g_wpr[(size_t)Cc * Cc];        // w_proj rounded

// ===========================================================================
// Helpers (sm_80+ PTX only — toolchain targets sm_103 w/o 'a': no tcgen05)
// ===========================================================================
__device__ __forceinline__ uint32_t smem_u32(const void* p) {
    uint32_t a;
    asm("{ .reg .u64 t; cvta.to.shared.u64 t, %1; cvt.u32.u64 %0, t; }"
        : "=r"(a) : "l"(p));
    return a;
}
// f32 -> tf32 round-to-nearest (bit pattern is a valid f32)
__device__ __forceinline__ uint32_t f2tf32(float x) {
    uint32_t y;
    asm("cvt.rna.tf32.f32 %0, %1;" : "=r"(y) : "f"(x));
    return y;
}
// D = A@B + D, m16n8k8 tf32
__device__ __forceinline__ void mma_tf32(float* c, const uint32_t* a, const uint32_t* b) {
    asm volatile(
        "mma.sync.aligned.m16n8k8.row.col.f32.tf32.tf32.f32 "
        "{%0,%1,%2,%3}, {%4,%5,%6,%7}, {%8,%9}, {%0,%1,%2,%3};"
        : "+f"(c[0]), "+f"(c[1]), "+f"(c[2]), "+f"(c[3])
        : "r"(a[0]), "r"(a[1]), "r"(a[2]), "r"(a[3]), "r"(b[0]), "r"(b[1]));
}
#define CP16(smem, gmem) \
    asm volatile("cp.async.cg.shared.global [%0], [%1], 16;" \
                 :: "r"(smem), "l"(gmem) : "memory")
#define CP_COMMIT() asm volatile("cp.async.commit_group;" ::: "memory")
#define CP_WAIT0()  asm volatile("cp.async.wait_group 0;" ::: "memory")
#define CP_WAIT1()  asm volatile("cp.async.wait_group 1;" ::: "memory")
#define CP_WAIT2()  asm volatile("cp.async.wait_group 2;" ::: "memory")

// ===========================================================================
// Pre-round pass: gmem fp32 -> tf32-rounded fp32 (hoists cvt out of all loops)
// ===========================================================================
__global__ __launch_bounds__(256) void round_tf32_kernel(
    const float4* __restrict__ in, float4* __restrict__ out, int n4)
{
    int i = blockIdx.x * blockDim.x + threadIdx.x;
    if (i < n4) {
        float4 v = in[i];
        v.x = __uint_as_float(f2tf32(v.x));
        v.y = __uint_as_float(f2tf32(v.y));
        v.z = __uint_as_float(f2tf32(v.z));
        v.w = __uint_as_float(f2tf32(v.w));
        out[i] = v;
    }
}

// ===========================================================================
// TF32 GEMM: C[M,N] = A[M,K] @ B[N,K]^T  (row-major, dims %128==0, pre-rounded)
// 128x128 CTA tile, BK=32, 256 thr (8 warps, 2x4 grid, 64x32/warp).
// 3-stage cp.async pipeline. Smem stride 36: fragment gather conflict-free.
// ===========================================================================
#define GA_ST   36
#define GTILE   (128 * GA_ST)
#define GEMM_SMEM (3 * 2 * GTILE * 4)         // 110592 B

template <bool ROUND_OUT>
__global__ __launch_bounds__(256) void gemm_tc_kernel(
    const float* __restrict__ A, const float* __restrict__ B,
    float* __restrict__ C, int N, int K)
{
    extern __shared__ float sg[];
    const uint32_t sb = smem_u32(sg);
    const int tid = threadIdx.x;
    const int wid = tid >> 5, lane = tid & 31;
    const int gr = lane >> 2, gc = lane & 3;
    const int m0 = blockIdx.y * 128, n0 = blockIdx.x * 128;
    const int wm0 = (wid >> 2) * 64, wn0 = (wid & 3) * 32;

    float acc[4][4][4];
    #pragma unroll
    for (int i = 0; i < 4; i++)
        #pragma unroll
        for (int j = 0; j < 4; j++)
            #pragma unroll
            for (int r = 0; r < 4; r++) acc[i][j][r] = 0.0f;

    const int r0 = tid >> 3;
    const int c4 = (tid & 7) * 4;
    const float* Ag = A + (size_t)(m0 + r0) * K + c4;
    const float* Bg = B + (size_t)(n0 + r0) * K + c4;
    const int KCH = K / 32;

    // prefetch chunks 0, 1
    #pragma unroll
    for (int s = 0; s < 2; s++) {
        #pragma unroll
        for (int it = 0; it < 4; it++) {
            uint32_t so = sb + (uint32_t)((s * 2 * GTILE +
                             (r0 + it * 32) * GA_ST + c4) * 4);
            CP16(so,             Ag + (size_t)it * 32 * K + s * 32);
            CP16(so + GTILE * 4, Bg + (size_t)it * 32 * K + s * 32);
        }
        CP_COMMIT();
    }

    for (int c = 0; c < KCH; c++) {
        if (c + 2 < KCH) {
            const int nb = (c + 2) % 3;
            #pragma unroll
            for (int it = 0; it < 4; it++) {
                uint32_t so = sb + (uint32_t)((nb * 2 * GTILE +
                                 (r0 + it * 32) * GA_ST + c4) * 4);
                CP16(so,             Ag + (size_t)it * 32 * K + (c + 2) * 32);
                CP16(so + GTILE * 4, Bg + (size_t)it * 32 * K + (c + 2) * 32);
            }
            CP_COMMIT();
            CP_WAIT2();
        } else if (c + 1 < KCH) {
            CP_WAIT1();
        } else {
            CP_WAIT0();
        }
        __syncthreads();

        const uint32_t* As = (const uint32_t*)(sg + (c % 3) * 2 * GTILE);
        const uint32_t* Bs = As + GTILE;
        #pragma unroll
        for (int ks = 0; ks < 4; ks++) {
            uint32_t af[4][4], bf[4][2];
            #pragma unroll
            for (int i = 0; i < 4; i++) {
                const uint32_t* ap = As + (wm0 + i * 16 + gr) * GA_ST + ks * 8 + gc;
                af[i][0] = ap[0];
                af[i][1] = ap[8 * GA_ST];
                af[i][2] = ap[4];
                af[i][3] = ap[8 * GA_ST + 4];
            }
            #pragma unroll
            for (int j = 0; j < 4; j++) {
                const uint32_t* bp = Bs + (wn0 + j * 8 + gr) * GA_ST + ks * 8 + gc;
                bf[j][0] = bp[0];
                bf[j][1] = bp[4];
            }
            #pragma unroll
            for (int i = 0; i < 4; i++)
                #pragma unroll
                for (int j = 0; j < 4; j++)
                    mma_tf32(acc[i][j], af[i], bf[j]);
        }
        __syncthreads();
    }

    #pragma unroll
    for (int i = 0; i < 4; i++)
        #pragma unroll
        for (int j = 0; j < 4; j++) {
            float v[4];
            #pragma unroll
            for (int r = 0; r < 4; r++)
                v[r] = ROUND_OUT ? __uint_as_float(f2tf32(acc[i][j][r]))
                                 : acc[i][j][r];
            float* cr = C + (size_t)(m0 + wm0 + i * 16 + gr) * N
                          + n0 + wn0 + j * 8 + gc * 2;
            float2 v0 = { v[0], v[1] };
            float2 v1 = { v[2], v[3] };
            *(float2*)cr           = v0;
            *(float2*)(cr + 8 * N) = v1;
        }
}

// ===========================================================================
// Flash attention (causal) on mma.sync tf32. Inputs pre-rounded (g_qkv).
// CTA: 256 thr (8 warps), q-tile 128 (warp owns 16 rows), k-tile 64, D=64.
// Q register-resident; K/V double-buffered cp.async; fully-masked warp-tiles
// skipped (exact no-op). Output rounded to tf32 for the proj GEMM.
// ===========================================================================
#define KST 68
#define VST 72
#define PST 68
#define QROWS 128
#define FLASH_SMEM ((2 * 64 * KST + 2 * 64 * VST + QROWS * PST) * 4)  // 106496

__global__ __launch_bounds__(256) void flash_tc_kernel(
    const float* __restrict__ qkv, float* __restrict__ outp)
{
    extern __shared__ float sf[];
    float* Ksm = sf;                        // [2][64*KST]
    float* Vsm = sf + 2 * 64 * KST;         // [2][64*VST]
    float* Psm = Vsm + 2 * 64 * VST;        // [128*PST]
    const uint32_t sb = smem_u32(sf);

    const int tid = threadIdx.x;
    const int wid = tid >> 5, lane = tid & 31;
    const int gr = lane >> 2, gc = lane & 3;
    const int qt = gridDim.x - 1 - blockIdx.x;      // heavy tiles first
    const int b  = blockIdx.y >> 4;
    const int h  = blockIdx.y & 15;
    const int q0 = qt * QROWS;
    const int wq0 = wid * 16;
    const size_t rst = 3 * Cc;

    // ---- Q fragments (pre-rounded; *0.125 is exact) ----
    uint32_t qf[8][4];
    {
        const float* qb  = qkv + (size_t)(b * Tn + q0 + wq0) * rst + h * HD;
        const float* qlo = qb + (size_t)gr * rst;
        const float* qhi = qlo + 8 * rst;
        #pragma unroll
        for (int ks = 0; ks < 8; ks++) {
            qf[ks][0] = __float_as_uint(qlo[ks * 8 + gc]     * 0.125f);
            qf[ks][1] = __float_as_uint(qhi[ks * 8 + gc]     * 0.125f);
            qf[ks][2] = __float_as_uint(qlo[ks * 8 + gc + 4] * 0.125f);
            qf[ks][3] = __float_as_uint(qhi[ks * 8 + gc + 4] * 0.125f);
        }
    }

    float o[8][4];
    #pragma unroll
    for (int j = 0; j < 8; j++)
        #pragma unroll
        for (int r = 0; r < 4; r++) o[j][r] = 0.0f;
    float m_lo = -1e30f, m_hi = -1e30f, l_lo = 0.0f, l_hi = 0.0f;

    // K/V gmem->smem: 4 rows/thread (rows r0+16*it)
    const int r0 = tid >> 4;
    const int c4 = (tid & 15) * 4;
    const float* kb0 = qkv + (size_t)(b * Tn) * rst + Cc + h * HD;  // K base

    // prefetch kt=0
    #pragma unroll
    for (int it = 0; it < 4; it++) {
        const int row = r0 + it * 16;
        uint32_t ko = sb + (uint32_t)((row * KST + c4) * 4);
        uint32_t vo = sb + (uint32_t)((2 * 64 * KST + row * VST + c4) * 4);
        CP16(ko, kb0 + (size_t)row * rst + c4);
        CP16(vo, kb0 + (size_t)row * rst + Cc + c4);   // V = K base + Cc
    }
    CP_COMMIT();

    const int last = 2 * qt + 1;
    int buf = 0;
    for (int kt = 0; kt <= last; kt++) {
        if (kt < last) {
            const int nb = buf ^ 1;
            const float* kb = kb0 + (size_t)(kt + 1) * 64 * rst;
            #pragma unroll
            for (int it = 0; it < 4; it++) {
                const int row = r0 + it * 16;
                uint32_t ko = sb + (uint32_t)((nb * 64 * KST + row * KST + c4) * 4);
                uint32_t vo = sb + (uint32_t)((2 * 64 * KST + nb * 64 * VST +
                                               row * VST + c4) * 4);
                CP16(ko, kb + (size_t)row * rst + c4);
                CP16(vo, kb + (size_t)row * rst + Cc + c4);
            }
            CP_COMMIT();
            CP_WAIT1();
        } else {
            CP_WAIT0();
        }
        __syncthreads();

        const int k0 = kt * 64;
        // warp-tile fully masked? (exact no-op: alpha=1, sum=0) -> skip
        if (k0 <= q0 + wq0 + 15) {
            const uint32_t* Ks = (const uint32_t*)(Ksm + buf * 64 * KST);
            const uint32_t* Vs = (const uint32_t*)(Vsm + buf * 64 * VST);

            // ---- S = Q @ K^T ----
            float s[8][4];
            #pragma unroll
            for (int j = 0; j < 8; j++)
                #pragma unroll
                for (int r = 0; r < 4; r++) s[j][r] = 0.0f;

            #pragma unroll
            for (int ks = 0; ks < 8; ks++) {
                #pragma unroll
                for (int j = 0; j < 8; j++) {
                    uint32_t bf[2];
                    const uint32_t* kp = Ks + (j * 8 + gr) * KST + ks * 8 + gc;
                    bf[0] = kp[0];
                    bf[1] = kp[4];
                    mma_tf32(s[j], qf[ks], bf);
                }
            }

            // ---- causal mask (only near the diagonal) ----
            if (k0 + 63 > q0 + wq0) {
                const int rlo = q0 + wq0 + gr, rhi = rlo + 8;
                #pragma unroll
                for (int j = 0; j < 8; j++) {
                    const int col = k0 + j * 8 + gc * 2;
                    if (col     > rlo) s[j][0] = -1e30f;
                    if (col + 1 > rlo) s[j][1] = -1e30f;
                    if (col     > rhi) s[j][2] = -1e30f;
                    if (col + 1 > rhi) s[j][3] = -1e30f;
                }
            }

            // ---- online softmax (rows lo = gr, hi = gr+8) ----
            {
                float mx_lo = -1e30f, mx_hi = -1e30f;
                #pragma unroll
                for (int j = 0; j < 8; j++) {
                    mx_lo = fmaxf(mx_lo, fmaxf(s[j][0], s[j][1]));
                    mx_hi = fmaxf(mx_hi, fmaxf(s[j][2], s[j][3]));
                }
                mx_lo = fmaxf(mx_lo, __shfl_xor_sync(0xffffffffu, mx_lo, 1));
                mx_lo = fmaxf(mx_lo, __shfl_xor_sync(0xffffffffu, mx_lo, 2));
                mx_hi = fmaxf(mx_hi, __shfl_xor_sync(0xffffffffu, mx_hi, 1));
                mx_hi = fmaxf(mx_hi, __shfl_xor_sync(0xffffffffu, mx_hi, 2));

                const float nm_lo = fmaxf(m_lo, mx_lo);
                const float nm_hi = fmaxf(m_hi, mx_hi);
                const float al_lo = __expf(m_lo - nm_lo);
                const float al_hi = __expf(m_hi - nm_hi);
                m_lo = nm_lo; m_hi = nm_hi;

                float sm_lo = 0.0f, sm_hi = 0.0f;
                #pragma unroll
                for (int j = 0; j < 8; j++) {
                    s[j][0] = __expf(s[j][0] - nm_lo);
                    s[j][1] = __expf(s[j][1] - nm_lo);
                    s[j][2] = __expf(s[j][2] - nm_hi);
                    s[j][3] = __expf(s[j][3] - nm_hi);
                    sm_lo += s[j][0] + s[j][1];
                    sm_hi += s[j][2] + s[j][3];
                }
                sm_lo += __shfl_xor_sync(0xffffffffu, sm_lo, 1);
                sm_lo += __shfl_xor_sync(0xffffffffu, sm_lo, 2);
                sm_hi += __shfl_xor_sync(0xffffffffu, sm_hi, 1);
                sm_hi += __shfl_xor_sync(0xffffffffu, sm_hi, 2);
                l_lo = l_lo * al_lo + sm_lo;
                l_hi = l_hi * al_hi + sm_hi;

                #pragma unroll
                for (int j = 0; j < 8; j++) {
                    o[j][0] *= al_lo; o[j][1] *= al_lo;
                    o[j][2] *= al_hi; o[j][3] *= al_hi;
                }
            }

            // ---- P (tf32 bits) -> warp-private Psm rows ----
            {
                uint32_t* pp = (uint32_t*)Psm + (wq0 + gr) * PST + gc * 2;
                #pragma unroll
                for (int j = 0; j < 8; j++) {
                    uint2 v0 = { f2tf32(s[j][0]), f2tf32(s[j][1]) };
                    uint2 v1 = { f2tf32(s[j][2]), f2tf32(s[j][3]) };
                    *(uint2*)(pp + j * 8)           = v0;
                    *(uint2*)(pp + j * 8 + 8 * PST) = v1;
                }
            }
            __syncwarp();

            // ---- O += P @ V ----
            #pragma unroll
            for (int kk = 0; kk < 8; kk++) {
                uint32_t pf[4];
                const uint32_t* pq = (const uint32_t*)Psm +
                                     (wq0 + gr) * PST + kk * 8 + gc;
                pf[0] = pq[0];
                pf[1] = pq[8 * PST];
                pf[2] = pq[4];
                pf[3] = pq[8 * PST + 4];
                #pragma unroll
                for (int j2 = 0; j2 < 8; j2++) {
                    uint32_t vf[2];
                    const uint32_t* vp = Vs + (kk * 8 + gc) * VST + j2 * 8 + gr;
                    vf[0] = vp[0];
                    vf[1] = vp[4 * VST];
                    mma_tf32(o[j2], pf, vf);
                }
            }
            __syncwarp();
        }
        __syncthreads();        // K/V buffer reads done before overwrite
        buf ^= 1;
    }

    // ---- normalize + round + write ----
    {
        const float il_lo = 1.0f / l_lo;
        const float il_hi = 1.0f / l_hi;
        float* ob  = outp + (size_t)(b * Tn + q0 + wq0) * Cc + h * HD;
        float* olo = ob + (size_t)gr * Cc + gc * 2;
        float* ohi = olo + (size_t)8 * Cc;
        #pragma unroll
        for (int j2 = 0; j2 < 8; j2++) {
            float2 v0 = { __uint_as_float(f2tf32(o[j2][0] * il_lo)),
                          __uint_as_float(f2tf32(o[j2][1] * il_lo)) };
            float2 v1 = { __uint_as_float(f2tf32(o[j2][2] * il_hi)),
                          __uint_as_float(f2tf32(o[j2][3] * il_hi)) };
            *(float2*)(olo + j2 * 8) = v0;
            *(float2*)(ohi + j2 * 8) = v1;
        }
    }
}

// ===========================================================================
// Launch
// ===========================================================================
extern "C" void kernel_launch(void* const* d_in, const int* in_sizes, int n_in,
                              void* d_out, int out_size)
{
    const float* x      = (const float*)d_in[0];   // (B,T,C)
    const float* w_attn = (const float*)d_in[1];   // (3C, C)
    const float* w_proj = (const float*)d_in[2];   // (C, C)
    float* out = (float*)d_out;                    // (B,T,C)

    float *qkv_p, *att_p, *xr_p, *war_p, *wpr_p;
    cudaGetSymbolAddress((void**)&qkv_p, g_qkv);
    cudaGetSymbolAddress((void**)&att_p, g_att);
    cudaGetSymbolAddress((void**)&xr_p,  g_xr);
    cudaGetSymbolAddress((void**)&war_p, g_war);
    cudaGetSymbolAddress((void**)&wpr_p, g_wpr);

    cudaFuncSetAttribute(gemm_tc_kernel<true>,
                         cudaFuncAttributeMaxDynamicSharedMemorySize, GEMM_SMEM);
    cudaFuncSetAttribute(gemm_tc_kernel<false>,
                         cudaFuncAttributeMaxDynamicSharedMemorySize, GEMM_SMEM);
    cudaFuncSetAttribute(flash_tc_kernel,
                         cudaFuncAttributeMaxDynamicSharedMemorySize, FLASH_SMEM);

    // 0) pre-round inputs to tf32
    {
        int n4x = MTOT * Cc / 4;
        round_tf32_kernel<<<n4x / 256, 256>>>((const float4*)x, (float4*)xr_p, n4x);
        int n4a = 3 * Cc * Cc / 4;
        round_tf32_kernel<<<n4a / 256, 256>>>((const float4*)w_attn, (float4*)war_p, n4a);
        int n4p = Cc * Cc / 4;
        round_tf32_kernel<<<n4p / 256, 256>>>((const float4*)w_proj, (float4*)wpr_p, n4p);
    }

    // 1) QKV = x @ w_attn^T : M=8192, N=3072, K=1024 (output rounded)
    {
        dim3 grid(3 * Cc / 128, MTOT / 128);
        gemm_tc_kernel<true><<<grid, 256, GEMM_SMEM>>>(xr_p, war_p, qkv_p, 3 * Cc, Cc);
    }

    // 2) Flash attention (tf32 mma; output rounded)
    {
        dim3 grid(Tn / QROWS, Bn * NH);
        flash_tc_kernel<<<grid, 256, FLASH_SMEM>>>(qkv_p, att_p);
    }

    // 3) out = att @ w_proj^T : M=8192, N=1024, K=1024 (raw fp32 output)
    {
        dim3 grid(Cc / 128, MTOT / 128);
        gemm_tc_kernel<false><<<grid, 256, GEMM_SMEM>>>(att_p, wpr_p, out, Cc, Cc);
    }
}

// round 9
// speedup vs baseline: 1.0677x; 1.0677x over previous
#include <cuda_runtime.h>
#include <math.h>
#include <stdint.h>

// Problem constants (B=4, T=2048, C=1024, H=16, D=64)
#define Bn   4
#define Tn   2048
#define Cc   1024
#define NH   16
#define HD   64
#define MTOT (Bn * Tn)          // 8192 rows

// Scratch (device globals: allocation is forbidden)
__device__ float g_qkv[(size_t)MTOT * 3 * Cc];  // (B*T, 3C), tf32-rounded
__device__ float g_att[(size_t)MTOT * Cc];      // (B*T, C),  tf32-rounded
__device__ float g_xr [(size_t)MTOT * Cc];      // x rounded
__device__ float g_war[(size_t)3 * Cc * Cc];    // w_attn rounded
__device__ float g_wpr[(size_t)Cc * Cc];        // w_proj rounded

// ===========================================================================
// Helpers (sm_80+ PTX only — toolchain targets sm_103 w/o 'a': no tcgen05)
// ===========================================================================
__device__ __forceinline__ uint32_t smem_u32(const void* p) {
    uint32_t a;
    asm("{ .reg .u64 t; cvta.to.shared.u64 t, %1; cvt.u32.u64 %0, t; }"
        : "=r"(a) : "l"(p));
    return a;
}
__device__ __forceinline__ uint32_t f2tf32(float x) {
    uint32_t y;
    asm("cvt.rna.tf32.f32 %0, %1;" : "=r"(y) : "f"(x));
    return y;
}
// D = A@B + D, m16n8k8 tf32
__device__ __forceinline__ void mma_tf32(float* c, const uint32_t* a, const uint32_t* b) {
    asm volatile(
        "mma.sync.aligned.m16n8k8.row.col.f32.tf32.tf32.f32 "
        "{%0,%1,%2,%3}, {%4,%5,%6,%7}, {%8,%9}, {%0,%1,%2,%3};"
        : "+f"(c[0]), "+f"(c[1]), "+f"(c[2]), "+f"(c[3])
        : "r"(a[0]), "r"(a[1]), "r"(a[2]), "r"(a[3]), "r"(b[0]), "r"(b[1]));
}
#define CP16(smem, gmem) \
    asm volatile("cp.async.cg.shared.global [%0], [%1], 16;" \
                 :: "r"(smem), "l"(gmem) : "memory")
#define CP_COMMIT() asm volatile("cp.async.commit_group;" ::: "memory")
#define CP_WAIT0()  asm volatile("cp.async.wait_group 0;" ::: "memory")
#define CP_WAIT1()  asm volatile("cp.async.wait_group 1;" ::: "memory")
#define CP_WAIT2()  asm volatile("cp.async.wait_group 2;" ::: "memory")

// ===========================================================================
// Pre-round pass: gmem fp32 -> tf32-rounded fp32
// ===========================================================================
__global__ __launch_bounds__(256) void round_tf32_kernel(
    const float4* __restrict__ in, float4* __restrict__ out, int n4)
{
    int i = blockIdx.x * blockDim.x + threadIdx.x;
    if (i < n4) {
        float4 v = in[i];
        v.x = __uint_as_float(f2tf32(v.x));
        v.y = __uint_as_float(f2tf32(v.y));
        v.z = __uint_as_float(f2tf32(v.z));
        v.w = __uint_as_float(f2tf32(v.w));
        out[i] = v;
    }
}

// ===========================================================================
// TF32 GEMM: C[M,N] = A[M,K] @ B[N,K]^T (row-major, M%128==0, N%256==0, K%32==0)
// CTA tile 128x256, BK=32, 256 thr (8 warps 2x4, 64x64 per warp -> 1.0 LDS/mma)
// 3-stage cp.async. Smem stride 36: all fragment gathers conflict-free.
// ===========================================================================
#define GA_ST   36
#define ATILE   (128 * GA_ST)                 // floats
#define BTILE   (256 * GA_ST)
#define GSTAGE  (ATILE + BTILE)               // 13824 floats = 55296 B
#define GEMM_SMEM (3 * GSTAGE * 4)            // 165888 B

template <bool ROUND_OUT>
__global__ __launch_bounds__(256) void gemm_tc_kernel(
    const float* __restrict__ A, const float* __restrict__ B,
    float* __restrict__ C, int N, int K)
{
    extern __shared__ float sg[];
    const uint32_t sb = smem_u32(sg);
    const int tid = threadIdx.x;
    const int wid = tid >> 5, lane = tid & 31;
    const int gr = lane >> 2, gc = lane & 3;
    const int m0 = blockIdx.y * 128, n0 = blockIdx.x * 256;
    const int wm0 = (wid >> 2) * 64, wn0 = (wid & 3) * 64;

    float acc[4][8][4];
    #pragma unroll
    for (int i = 0; i < 4; i++)
        #pragma unroll
        for (int j = 0; j < 8; j++)
            #pragma unroll
            for (int r = 0; r < 4; r++) acc[i][j][r] = 0.0f;

    const int r0 = tid >> 3;            // 0..31
    const int c4 = (tid & 7) * 4;
    const float* Ag = A + (size_t)(m0 + r0) * K + c4;
    const float* Bg = B + (size_t)(n0 + r0) * K + c4;
    const int KCH = K / 32;

    // prefetch chunks 0, 1
    #pragma unroll
    for (int s = 0; s < 2; s++) {
        const uint32_t st = sb + (uint32_t)(s * GSTAGE * 4);
        #pragma unroll
        for (int it = 0; it < 4; it++)
            CP16(st + (uint32_t)(((r0 + it * 32) * GA_ST + c4) * 4),
                 Ag + (size_t)it * 32 * K + s * 32);
        #pragma unroll
        for (int it = 0; it < 8; it++)
            CP16(st + (uint32_t)((ATILE + (r0 + it * 32) * GA_ST + c4) * 4),
                 Bg + (size_t)it * 32 * K + s * 32);
        CP_COMMIT();
    }

    for (int c = 0; c < KCH; c++) {
        if (c + 2 < KCH) {
            const uint32_t st = sb + (uint32_t)(((c + 2) % 3) * GSTAGE * 4);
            #pragma unroll
            for (int it = 0; it < 4; it++)
                CP16(st + (uint32_t)(((r0 + it * 32) * GA_ST + c4) * 4),
                     Ag + (size_t)it * 32 * K + (c + 2) * 32);
            #pragma unroll
            for (int it = 0; it < 8; it++)
                CP16(st + (uint32_t)((ATILE + (r0 + it * 32) * GA_ST + c4) * 4),
                     Bg + (size_t)it * 32 * K + (c + 2) * 32);
            CP_COMMIT();
            CP_WAIT2();
        } else if (c + 1 < KCH) {
            CP_WAIT1();
        } else {
            CP_WAIT0();
        }
        __syncthreads();

        const uint32_t* As = (const uint32_t*)(sg + (c % 3) * GSTAGE);
        const uint32_t* Bs = As + ATILE;
        #pragma unroll
        for (int ks = 0; ks < 4; ks++) {
            uint32_t af[4][4], bf[8][2];
            #pragma unroll
            for (int i = 0; i < 4; i++) {
                const uint32_t* ap = As + (wm0 + i * 16 + gr) * GA_ST + ks * 8 + gc;
                af[i][0] = ap[0];
                af[i][1] = ap[8 * GA_ST];
                af[i][2] = ap[4];
                af[i][3] = ap[8 * GA_ST + 4];
            }
            #pragma unroll
            for (int j = 0; j < 8; j++) {
                const uint32_t* bp = Bs + (wn0 + j * 8 + gr) * GA_ST + ks * 8 + gc;
                bf[j][0] = bp[0];
                bf[j][1] = bp[4];
            }
            #pragma unroll
            for (int i = 0; i < 4; i++)
                #pragma unroll
                for (int j = 0; j < 8; j++)
                    mma_tf32(acc[i][j], af[i], bf[j]);
        }
        __syncthreads();
    }

    #pragma unroll
    for (int i = 0; i < 4; i++)
        #pragma unroll
        for (int j = 0; j < 8; j++) {
            float v[4];
            #pragma unroll
            for (int r = 0; r < 4; r++)
                v[r] = ROUND_OUT ? __uint_as_float(f2tf32(acc[i][j][r]))
                                 : acc[i][j][r];
            float* cr = C + (size_t)(m0 + wm0 + i * 16 + gr) * N
                          + n0 + wn0 + j * 8 + gc * 2;
            float2 v0 = { v[0], v[1] };
            float2 v1 = { v[2], v[3] };
            *(float2*)cr           = v0;
            *(float2*)(cr + 8 * N) = v1;
        }
}

// ===========================================================================
// Flash attention (causal) on mma.sync tf32. Inputs pre-rounded (g_qkv).
// CTA: 128 thr (4 warps), q-tile 128 (warp owns 32 rows = 2 row-groups),
// k-tile 64, D=64. K/V fragments shared by both row-groups per load.
// ===========================================================================
#define KST 68
#define VST 72
#define PST 68
#define QROWS 128
#define FLASH_SMEM ((2 * 64 * KST + 2 * 64 * VST + QROWS * PST) * 4)  // 106496

__global__ __launch_bounds__(128) void flash_tc_kernel(
    const float* __restrict__ qkv, float* __restrict__ outp)
{
    extern __shared__ float sf[];
    float* Ksm = sf;                        // [2][64*KST]
    float* Vsm = sf + 2 * 64 * KST;         // [2][64*VST]
    float* Psm = Vsm + 2 * 64 * VST;        // [128*PST]
    const uint32_t sb = smem_u32(sf);

    const int tid = threadIdx.x;
    const int wid = tid >> 5, lane = tid & 31;
    const int gr = lane >> 2, gc = lane & 3;
    const int qt = gridDim.x - 1 - blockIdx.x;      // heavy tiles first
    const int b  = blockIdx.y >> 4;
    const int h  = blockIdx.y & 15;
    const int q0 = qt * QROWS;
    const int wq0 = wid * 32;               // warp's 32 q-rows
    const size_t rst = 3 * Cc;

    // ---- Q fragments: 2 row-groups x 8 k-blocks x 4 regs (pre-rounded) ----
    uint32_t qf[2][8][4];
    #pragma unroll
    for (int rg = 0; rg < 2; rg++) {
        const float* qlo = qkv + (size_t)(b * Tn + q0 + wq0 + rg * 16 + gr) * rst
                               + h * HD;
        const float* qhi = qlo + 8 * rst;
        #pragma unroll
        for (int ks = 0; ks < 8; ks++) {
            qf[rg][ks][0] = __float_as_uint(qlo[ks * 8 + gc]     * 0.125f);
            qf[rg][ks][1] = __float_as_uint(qhi[ks * 8 + gc]     * 0.125f);
            qf[rg][ks][2] = __float_as_uint(qlo[ks * 8 + gc + 4] * 0.125f);
            qf[rg][ks][3] = __float_as_uint(qhi[ks * 8 + gc + 4] * 0.125f);
        }
    }

    float o[2][8][4];
    #pragma unroll
    for (int rg = 0; rg < 2; rg++)
        #pragma unroll
        for (int j = 0; j < 8; j++)
            #pragma unroll
            for (int r = 0; r < 4; r++) o[rg][j][r] = 0.0f;
    float m_lo[2] = {-1e30f, -1e30f}, m_hi[2] = {-1e30f, -1e30f};
    float l_lo[2] = {0.0f, 0.0f},     l_hi[2] = {0.0f, 0.0f};

    // K/V gmem->smem: 128 thr, 8 rows/thread (rows r0+8*it)
    const int r0 = tid >> 4;
    const int c4 = (tid & 15) * 4;
    const float* kb0 = qkv + (size_t)(b * Tn) * rst + Cc + h * HD;  // K base

    #pragma unroll
    for (int it = 0; it < 8; it++) {
        const int row = r0 + it * 8;
        CP16(sb + (uint32_t)((row * KST + c4) * 4),
             kb0 + (size_t)row * rst + c4);
        CP16(sb + (uint32_t)((2 * 64 * KST + row * VST + c4) * 4),
             kb0 + (size_t)row * rst + Cc + c4);    // V = K + Cc
    }
    CP_COMMIT();

    const int last = 2 * qt + 1;
    int buf = 0;
    for (int kt = 0; kt <= last; kt++) {
        if (kt < last) {
            const int nb = buf ^ 1;
            const float* kb = kb0 + (size_t)(kt + 1) * 64 * rst;
            #pragma unroll
            for (int it = 0; it < 8; it++) {
                const int row = r0 + it * 8;
                CP16(sb + (uint32_t)((nb * 64 * KST + row * KST + c4) * 4),
                     kb + (size_t)row * rst + c4);
                CP16(sb + (uint32_t)((2 * 64 * KST + nb * 64 * VST +
                                      row * VST + c4) * 4),
                     kb + (size_t)row * rst + Cc + c4);
            }
            CP_COMMIT();
            CP_WAIT1();
        } else {
            CP_WAIT0();
        }
        __syncthreads();

        const int k0 = kt * 64;
        // warp tile fully masked? (exact no-op) -> skip
        if (k0 <= q0 + wq0 + 31) {
            const uint32_t* Ks = (const uint32_t*)(Ksm + buf * 64 * KST);
            const uint32_t* Vs = (const uint32_t*)(Vsm + buf * 64 * VST);

            // ---- S = Q @ K^T (K frags shared by both row-groups) ----
            float s[2][8][4];
            #pragma unroll
            for (int rg = 0; rg < 2; rg++)
                #pragma unroll
                for (int j = 0; j < 8; j++)
                    #pragma unroll
                    for (int r = 0; r < 4; r++) s[rg][j][r] = 0.0f;

            #pragma unroll
            for (int ks = 0; ks < 8; ks++) {
                #pragma unroll
                for (int j = 0; j < 8; j++) {
                    uint32_t bf[2];
                    const uint32_t* kp = Ks + (j * 8 + gr) * KST + ks * 8 + gc;
                    bf[0] = kp[0];
                    bf[1] = kp[4];
                    mma_tf32(s[0][j], qf[0][ks], bf);
                    mma_tf32(s[1][j], qf[1][ks], bf);
                }
            }

            // ---- per row-group: mask, softmax, P store ----
            #pragma unroll
            for (int rg = 0; rg < 2; rg++) {
                const int rb = q0 + wq0 + rg * 16;
                if (k0 + 63 > rb) {
                    const int rlo = rb + gr, rhi = rlo + 8;
                    #pragma unroll
                    for (int j = 0; j < 8; j++) {
                        const int col = k0 + j * 8 + gc * 2;
                        if (col     > rlo) s[rg][j][0] = -1e30f;
                        if (col + 1 > rlo) s[rg][j][1] = -1e30f;
                        if (col     > rhi) s[rg][j][2] = -1e30f;
                        if (col + 1 > rhi) s[rg][j][3] = -1e30f;
                    }
                }

                float mx_lo = -1e30f, mx_hi = -1e30f;
                #pragma unroll
                for (int j = 0; j < 8; j++) {
                    mx_lo = fmaxf(mx_lo, fmaxf(s[rg][j][0], s[rg][j][1]));
                    mx_hi = fmaxf(mx_hi, fmaxf(s[rg][j][2], s[rg][j][3]));
                }
                mx_lo = fmaxf(mx_lo, __shfl_xor_sync(0xffffffffu, mx_lo, 1));
                mx_lo = fmaxf(mx_lo, __shfl_xor_sync(0xffffffffu, mx_lo, 2));
                mx_hi = fmaxf(mx_hi, __shfl_xor_sync(0xffffffffu, mx_hi, 1));
                mx_hi = fmaxf(mx_hi, __shfl_xor_sync(0xffffffffu, mx_hi, 2));

                const float nm_lo = fmaxf(m_lo[rg], mx_lo);
                const float nm_hi = fmaxf(m_hi[rg], mx_hi);
                const float al_lo = __expf(m_lo[rg] - nm_lo);
                const float al_hi = __expf(m_hi[rg] - nm_hi);
                m_lo[rg] = nm_lo; m_hi[rg] = nm_hi;

                float sm_lo = 0.0f, sm_hi = 0.0f;
                #pragma unroll
                for (int j = 0; j < 8; j++) {
                    s[rg][j][0] = __expf(s[rg][j][0] - nm_lo);
                    s[rg][j][1] = __expf(s[rg][j][1] - nm_lo);
                    s[rg][j][2] = __expf(s[rg][j][2] - nm_hi);
                    s[rg][j][3] = __expf(s[rg][j][3] - nm_hi);
                    sm_lo += s[rg][j][0] + s[rg][j][1];
                    sm_hi += s[rg][j][2] + s[rg][j][3];
                }
                sm_lo += __shfl_xor_sync(0xffffffffu, sm_lo, 1);
                sm_lo += __shfl_xor_sync(0xffffffffu, sm_lo, 2);
                sm_hi += __shfl_xor_sync(0xffffffffu, sm_hi, 1);
                sm_hi += __shfl_xor_sync(0xffffffffu, sm_hi, 2);
                l_lo[rg] = l_lo[rg] * al_lo + sm_lo;
                l_hi[rg] = l_hi[rg] * al_hi + sm_hi;

                #pragma unroll
                for (int j = 0; j < 8; j++) {
                    o[rg][j][0] *= al_lo; o[rg][j][1] *= al_lo;
                    o[rg][j][2] *= al_hi; o[rg][j][3] *= al_hi;
                }

                uint32_t* pp = (uint32_t*)Psm + (wq0 + rg * 16 + gr) * PST + gc * 2;
                #pragma unroll
                for (int j = 0; j < 8; j++) {
                    uint2 v0 = { f2tf32(s[rg][j][0]), f2tf32(s[rg][j][1]) };
                    uint2 v1 = { f2tf32(s[rg][j][2]), f2tf32(s[rg][j][3]) };
                    *(uint2*)(pp + j * 8)           = v0;
                    *(uint2*)(pp + j * 8 + 8 * PST) = v1;
                }
            }
            __syncwarp();

            // ---- O += P @ V (V frags shared by both row-groups) ----
            #pragma unroll
            for (int kk = 0; kk < 8; kk++) {
                uint32_t pf[2][4];
                #pragma unroll
                for (int rg = 0; rg < 2; rg++) {
                    const uint32_t* pq = (const uint32_t*)Psm +
                                         (wq0 + rg * 16 + gr) * PST + kk * 8 + gc;
                    pf[rg][0] = pq[0];
                    pf[rg][1] = pq[8 * PST];
                    pf[rg][2] = pq[4];
                    pf[rg][3] = pq[8 * PST + 4];
                }
                #pragma unroll
                for (int j2 = 0; j2 < 8; j2++) {
                    uint32_t vf[2];
                    const uint32_t* vp = Vs + (kk * 8 + gc) * VST + j2 * 8 + gr;
                    vf[0] = vp[0];
                    vf[1] = vp[4 * VST];
                    mma_tf32(o[0][j2], pf[0], vf);
                    mma_tf32(o[1][j2], pf[1], vf);
                }
            }
            __syncwarp();
        }
        __syncthreads();        // K/V buffer reads done before overwrite
        buf ^= 1;
    }

    // ---- normalize + round + write ----
    #pragma unroll
    for (int rg = 0; rg < 2; rg++) {
        const float il_lo = 1.0f / l_lo[rg];
        const float il_hi = 1.0f / l_hi[rg];
        float* olo = outp + (size_t)(b * Tn + q0 + wq0 + rg * 16 + gr) * Cc
                          + h * HD + gc * 2;
        float* ohi = olo + (size_t)8 * Cc;
        #pragma unroll
        for (int j2 = 0; j2 < 8; j2++) {
            float2 v0 = { __uint_as_float(f2tf32(o[rg][j2][0] * il_lo)),
                          __uint_as_float(f2tf32(o[rg][j2][1] * il_lo)) };
            float2 v1 = { __uint_as_float(f2tf32(o[rg][j2][2] * il_hi)),
                          __uint_as_float(f2tf32(o[rg][j2][3] * il_hi)) };
            *(float2*)(olo + j2 * 8) = v0;
            *(float2*)(ohi + j2 * 8) = v1;
        }
    }
}

// ===========================================================================
// Launch
// ===========================================================================
extern "C" void kernel_launch(void* const* d_in, const int* in_sizes, int n_in,
                              void* d_out, int out_size)
{
    const float* x      = (const float*)d_in[0];   // (B,T,C)
    const float* w_attn = (const float*)d_in[1];   // (3C, C)
    const float* w_proj = (const float*)d_in[2];   // (C, C)
    float* out = (float*)d_out;                    // (B,T,C)

    float *qkv_p, *att_p, *xr_p, *war_p, *wpr_p;
    cudaGetSymbolAddress((void**)&qkv_p, g_qkv);
    cudaGetSymbolAddress((void**)&att_p, g_att);
    cudaGetSymbolAddress((void**)&xr_p,  g_xr);
    cudaGetSymbolAddress((void**)&war_p, g_war);
    cudaGetSymbolAddress((void**)&wpr_p, g_wpr);

    cudaFuncSetAttribute(gemm_tc_kernel<true>,
                         cudaFuncAttributeMaxDynamicSharedMemorySize, GEMM_SMEM);
    cudaFuncSetAttribute(gemm_tc_kernel<false>,
                         cudaFuncAttributeMaxDynamicSharedMemorySize, GEMM_SMEM);
    cudaFuncSetAttribute(flash_tc_kernel,
                         cudaFuncAttributeMaxDynamicSharedMemorySize, FLASH_SMEM);

    // 0) pre-round inputs to tf32
    {
        int n4x = MTOT * Cc / 4;
        round_tf32_kernel<<<n4x / 256, 256>>>((const float4*)x, (float4*)xr_p, n4x);
        int n4a = 3 * Cc * Cc / 4;
        round_tf32_kernel<<<n4a / 256, 256>>>((const float4*)w_attn, (float4*)war_p, n4a);
        int n4p = Cc * Cc / 4;
        round_tf32_kernel<<<n4p / 256, 256>>>((const float4*)w_proj, (float4*)wpr_p, n4p);
    }

    // 1) QKV = x @ w_attn^T : M=8192, N=3072, K=1024 (output rounded)
    {
        dim3 grid(3 * Cc / 256, MTOT / 128);
        gemm_tc_kernel<true><<<grid, 256, GEMM_SMEM>>>(xr_p, war_p, qkv_p, 3 * Cc, Cc);
    }

    // 2) Flash attention (tf32 mma; output rounded)
    {
        dim3 grid(Tn / QROWS, Bn * NH);
        flash_tc_kernel<<<grid, 128, FLASH_SMEM>>>(qkv_p, att_p);
    }

    // 3) out = att @ w_proj^T : M=8192, N=1024, K=1024 (raw fp32 output)
    {
        dim3 grid(Cc / 256, MTOT / 128);
        gemm_tc_kernel<false><<<grid, 256, GEMM_SMEM>>>(att_p, wpr_p, out, Cc, Cc);
    }
}

// round 10
// speedup vs baseline: 1.6362x; 1.5324x over previous
#include <cuda_runtime.h>
#include <cuda_fp16.h>
#include <math.h>
#include <stdint.h>

// Problem constants (B=4, T=2048, C=1024, H=16, D=64)
#define Bn   4
#define Tn   2048
#define Cc   1024
#define NH   16
#define HD   64
#define MTOT (Bn * Tn)          // 8192 rows

// Scratch (device globals: allocation is forbidden)
__device__ __half g_xh [(size_t)MTOT * Cc];        // x (half)
__device__ __half g_wah[(size_t)3 * Cc * Cc];      // w_attn (half)
__device__ __half g_wph[(size_t)Cc * Cc];          // w_proj (half)
__device__ __half g_qkh[(size_t)MTOT * 2 * Cc];    // q,k (half)  (B*T, 2C)
__device__ float  g_v  [(size_t)MTOT * Cc];        // v (f32)     (B*T, C)
__device__ __half g_ath[(size_t)MTOT * Cc];        // attention out (half)

// ===========================================================================
// Helpers
// ===========================================================================
__device__ __forceinline__ uint32_t smem_u32(const void* p) {
    uint32_t a;
    asm("{ .reg .u64 t; cvta.to.shared.u64 t, %1; cvt.u32.u64 %0, t; }"
        : "=r"(a) : "l"(p));
    return a;
}
__device__ __forceinline__ uint32_t f2tf32(float x) {
    uint32_t y;
    asm("cvt.rna.tf32.f32 %0, %1;" : "=r"(y) : "f"(x));
    return y;
}
// fp16 mma: D(16x8,f32) = A(16x16,f16,row) @ B(16x8,f16,col) + D
__device__ __forceinline__ void mma_f16(float* c, const uint32_t* a, const uint32_t* b) {
    asm volatile(
        "mma.sync.aligned.m16n8k16.row.col.f32.f16.f16.f32 "
        "{%0,%1,%2,%3}, {%4,%5,%6,%7}, {%8,%9}, {%0,%1,%2,%3};"
        : "+f"(c[0]), "+f"(c[1]), "+f"(c[2]), "+f"(c[3])
        : "r"(a[0]), "r"(a[1]), "r"(a[2]), "r"(a[3]), "r"(b[0]), "r"(b[1]));
}
// tf32 mma (kept for flash P@V)
__device__ __forceinline__ void mma_tf32(float* c, const uint32_t* a, const uint32_t* b) {
    asm volatile(
        "mma.sync.aligned.m16n8k8.row.col.f32.tf32.tf32.f32 "
        "{%0,%1,%2,%3}, {%4,%5,%6,%7}, {%8,%9}, {%0,%1,%2,%3};"
        : "+f"(c[0]), "+f"(c[1]), "+f"(c[2]), "+f"(c[3])
        : "r"(a[0]), "r"(a[1]), "r"(a[2]), "r"(a[3]), "r"(b[0]), "r"(b[1]));
}
#define CP16(smem, gmem) \
    asm volatile("cp.async.cg.shared.global [%0], [%1], 16;" \
                 :: "r"(smem), "l"(gmem) : "memory")
#define CP_COMMIT() asm volatile("cp.async.commit_group;" ::: "memory")
#define CP_WAIT0()  asm volatile("cp.async.wait_group 0;" ::: "memory")
#define CP_WAIT1()  asm volatile("cp.async.wait_group 1;" ::: "memory")
#define CP_WAIT2()  asm volatile("cp.async.wait_group 2;" ::: "memory")

// ===========================================================================
// Convert pass: fp32 -> fp16 (8 elems / thread, 16B stores)
// ===========================================================================
__global__ __launch_bounds__(256) void to_half_kernel(
    const float4* __restrict__ in, uint4* __restrict__ out, int n8)
{
    int i = blockIdx.x * blockDim.x + threadIdx.x;
    if (i < n8) {
        float4 a = in[2 * i], b = in[2 * i + 1];
        __half2 h0 = __floats2half2_rn(a.x, a.y);
        __half2 h1 = __floats2half2_rn(a.z, a.w);
        __half2 h2 = __floats2half2_rn(b.x, b.y);
        __half2 h3 = __floats2half2_rn(b.z, b.w);
        uint4 o = { *(uint32_t*)&h0, *(uint32_t*)&h1,
                    *(uint32_t*)&h2, *(uint32_t*)&h3 };
        out[i] = o;
    }
}

// ===========================================================================
// FP16 GEMM: C[M,N] = A[M,K] @ B[N,K]^T, A/B half K-major, acc f32.
// CTA 128x128, BK=32, 256 thr (8 warps 2x4, 64x32/warp), 3-stage cp.async.
// Smem stride 40 halves (80B): all half2 fragment gathers conflict-free,
// cp.async dst 16B-aligned (80 = 5*16).
// MODE 0: C = float* (stride N).  MODE 1: qkv split -> qk half / v f32.
// ===========================================================================
#define GH_ST  40
#define HTILE  (128 * GH_ST)                  // halves per (A or B) tile
#define HSTAGE (2 * HTILE)                    // 10240 halves = 20480 B
#define GEMM_SMEM (3 * HSTAGE * 2)            // 61440 B

template <int MODE>
__global__ __launch_bounds__(256, 2) void gemm_f16_kernel(
    const __half* __restrict__ A, const __half* __restrict__ B,
    float* __restrict__ C, __half* __restrict__ QKH, float* __restrict__ V,
    int N, int K)
{
    extern __shared__ char smc[];
    __half* sg = (__half*)smc;
    const uint32_t sb = smem_u32(sg);
    const int tid = threadIdx.x;
    const int wid = tid >> 5, lane = tid & 31;
    const int gr = lane >> 2, gc = lane & 3;
    const int m0 = blockIdx.y * 128, n0 = blockIdx.x * 128;
    const int wm0 = (wid >> 2) * 64, wn0 = (wid & 3) * 32;

    float acc[4][4][4];
    #pragma unroll
    for (int i = 0; i < 4; i++)
        #pragma unroll
        for (int j = 0; j < 4; j++)
            #pragma unroll
            for (int r = 0; r < 4; r++) acc[i][j][r] = 0.0f;

    const int r0 = tid >> 2;            // 0..63
    const int c8 = (tid & 3) * 8;       // 0,8,16,24 (halves)
    const __half* Ag = A + (size_t)(m0 + r0) * K + c8;
    const __half* Bg = B + (size_t)(n0 + r0) * K + c8;
    const size_t rowstep = (size_t)64 * K;
    const int KCH = K / 32;

    // prefetch chunks 0,1
    #pragma unroll
    for (int s = 0; s < 2; s++) {
        const uint32_t st = sb + (uint32_t)(s * HSTAGE * 2);
        #pragma unroll
        for (int it = 0; it < 2; it++) {
            uint32_t off = (uint32_t)(((r0 + it * 64) * GH_ST + c8) * 2);
            CP16(st + off,              Ag + it * rowstep + s * 32);
            CP16(st + off + HTILE * 2,  Bg + it * rowstep + s * 32);
        }
        CP_COMMIT();
    }

    for (int c = 0; c < KCH; c++) {
        if (c + 2 < KCH) {
            const uint32_t st = sb + (uint32_t)(((c + 2) % 3) * HSTAGE * 2);
            #pragma unroll
            for (int it = 0; it < 2; it++) {
                uint32_t off = (uint32_t)(((r0 + it * 64) * GH_ST + c8) * 2);
                CP16(st + off,             Ag + it * rowstep + (c + 2) * 32);
                CP16(st + off + HTILE * 2, Bg + it * rowstep + (c + 2) * 32);
            }
            CP_COMMIT();
            CP_WAIT2();
        } else if (c + 1 < KCH) {
            CP_WAIT1();
        } else {
            CP_WAIT0();
        }
        __syncthreads();

        const __half* As = sg + (c % 3) * HSTAGE;
        const __half* Bs = As + HTILE;
        #pragma unroll
        for (int ks = 0; ks < 2; ks++) {        // two k16 steps per chunk
            uint32_t af[4][4], bf[4][2];
            #pragma unroll
            for (int i = 0; i < 4; i++) {
                const __half* ap = As + (wm0 + i * 16 + gr) * GH_ST + ks * 16 + gc * 2;
                af[i][0] = *(const uint32_t*)(ap);
                af[i][1] = *(const uint32_t*)(ap + 8 * GH_ST);
                af[i][2] = *(const uint32_t*)(ap + 8);
                af[i][3] = *(const uint32_t*)(ap + 8 * GH_ST + 8);
            }
            #pragma unroll
            for (int j = 0; j < 4; j++) {
                const __half* bp = Bs + (wn0 + j * 8 + gr) * GH_ST + ks * 16 + gc * 2;
                bf[j][0] = *(const uint32_t*)(bp);
                bf[j][1] = *(const uint32_t*)(bp + 8);
            }
            #pragma unroll
            for (int i = 0; i < 4; i++)
                #pragma unroll
                for (int j = 0; j < 4; j++)
                    mma_f16(acc[i][j], af[i], bf[j]);
        }
        __syncthreads();
    }

    // epilogue
    #pragma unroll
    for (int i = 0; i < 4; i++)
        #pragma unroll
        for (int j = 0; j < 4; j++) {
            const int row = m0 + wm0 + i * 16 + gr;
            const int col = n0 + wn0 + j * 8 + gc * 2;
            if (MODE == 0) {
                float* cr = C + (size_t)row * N + col;
                float2 v0 = { acc[i][j][0], acc[i][j][1] };
                float2 v1 = { acc[i][j][2], acc[i][j][3] };
                *(float2*)cr           = v0;
                *(float2*)(cr + 8 * N) = v1;
            } else {
                if (n0 < 2 * Cc) {   // q,k -> half
                    __half2 h0 = __floats2half2_rn(acc[i][j][0], acc[i][j][1]);
                    __half2 h1 = __floats2half2_rn(acc[i][j][2], acc[i][j][3]);
                    __half2* qr = (__half2*)(QKH + (size_t)row * 2 * Cc + col);
                    *qr                    = h0;
                    *(__half2*)((__half*)qr + (size_t)8 * 2 * Cc) = h1;
                } else {             // v -> f32
                    float* vr = V + (size_t)row * Cc + (col - 2 * Cc);
                    float2 v0 = { acc[i][j][0], acc[i][j][1] };
                    float2 v1 = { acc[i][j][2], acc[i][j][3] };
                    *(float2*)vr           = v0;
                    *(float2*)(vr + 8 * Cc) = v1;
                }
            }
        }
}

// ===========================================================================
// Flash attention (causal). S = Q@K^T in fp16 mma (K=16/instr); softmax f32;
// P@V in tf32 mma (V f32 smem, proven layout). att out -> half.
// CTA: 128 thr (4 warps), q-tile 128 (warp owns 32 rows = 2 row-groups).
// ===========================================================================
#define KSTH 72                 // halves (144B rows: 16B-aligned, conflict-free)
#define VST  72                 // floats
#define PST  68                 // floats
#define QROWS 128
#define FLASH_SMEM (2*64*KSTH*2 + 2*64*VST*4 + QROWS*PST*4)   // 90112 B

__global__ __launch_bounds__(128, 2) void flash_tc_kernel(
    const __half* __restrict__ qkh, const float* __restrict__ vin,
    __half* __restrict__ outp)
{
    extern __shared__ char smc[];
    __half* Ksm = (__half*)smc;                          // [2][64*KSTH]
    float*  Vsm = (float*)(smc + 2 * 64 * KSTH * 2);     // [2][64*VST]
    float*  Psm = Vsm + 2 * 64 * VST;                    // [128*PST]
    const uint32_t sbK = smem_u32(Ksm);
    const uint32_t sbV = smem_u32(Vsm);

    const int tid = threadIdx.x;
    const int wid = tid >> 5, lane = tid & 31;
    const int gr = lane >> 2, gc = lane & 3;
    const int qt = gridDim.x - 1 - blockIdx.x;      // heavy tiles first
    const int b  = blockIdx.y >> 4;
    const int h  = blockIdx.y & 15;
    const int q0 = qt * QROWS;
    const int wq0 = wid * 32;
    const size_t qkst = 2 * Cc;                     // halves per row

    // ---- Q fragments: 2 row-groups x 4 k16-steps x 4 regs ----
    uint32_t qf[2][4][4];
    #pragma unroll
    for (int rg = 0; rg < 2; rg++) {
        const __half* qlo = qkh + (size_t)(b * Tn + q0 + wq0 + rg * 16 + gr) * qkst
                                + h * HD;
        const __half* qhi = qlo + 8 * qkst;
        #pragma unroll
        for (int ks = 0; ks < 4; ks++) {
            qf[rg][ks][0] = *(const uint32_t*)(qlo + ks * 16 + gc * 2);
            qf[rg][ks][1] = *(const uint32_t*)(qhi + ks * 16 + gc * 2);
            qf[rg][ks][2] = *(const uint32_t*)(qlo + ks * 16 + gc * 2 + 8);
            qf[rg][ks][3] = *(const uint32_t*)(qhi + ks * 16 + gc * 2 + 8);
        }
    }

    float o[2][8][4];
    #pragma unroll
    for (int rg = 0; rg < 2; rg++)
        #pragma unroll
        for (int j = 0; j < 8; j++)
            #pragma unroll
            for (int r = 0; r < 4; r++) o[rg][j][r] = 0.0f;
    float m_lo[2] = {-1e30f, -1e30f}, m_hi[2] = {-1e30f, -1e30f};
    float l_lo[2] = {0.0f, 0.0f},     l_hi[2] = {0.0f, 0.0f};

    // K loader: 64 rows x 64 halves; 4 CP16/thread
    const int rk = tid >> 3;            // 0..15
    const int ck = (tid & 7) * 8;       // halves
    // V loader: 64 rows x 64 floats; 8 CP16/thread
    const int rv = tid >> 4;            // 0..7
    const int cv = (tid & 15) * 4;      // floats
    const __half* kb0 = qkh + (size_t)(b * Tn) * qkst + Cc + h * HD;
    const float*  vb0 = vin + (size_t)(b * Tn) * Cc + h * HD;

    // prefetch kt=0
    {
        #pragma unroll
        for (int it = 0; it < 4; it++) {
            const int row = rk + it * 16;
            CP16(sbK + (uint32_t)((row * KSTH + ck) * 2),
                 kb0 + (size_t)row * qkst + ck);
        }
        #pragma unroll
        for (int it = 0; it < 8; it++) {
            const int row = rv + it * 8;
            CP16(sbV + (uint32_t)((row * VST + cv) * 4),
                 vb0 + (size_t)row * Cc + cv);
        }
        CP_COMMIT();
    }

    const int last = 2 * qt + 1;
    int buf = 0;
    for (int kt = 0; kt <= last; kt++) {
        if (kt < last) {
            const int nb = buf ^ 1;
            const __half* kb = kb0 + (size_t)(kt + 1) * 64 * qkst;
            const float*  vb = vb0 + (size_t)(kt + 1) * 64 * Cc;
            #pragma unroll
            for (int it = 0; it < 4; it++) {
                const int row = rk + it * 16;
                CP16(sbK + (uint32_t)(((nb * 64 + row) * KSTH + ck) * 2),
                     kb + (size_t)row * qkst + ck);
            }
            #pragma unroll
            for (int it = 0; it < 8; it++) {
                const int row = rv + it * 8;
                CP16(sbV + (uint32_t)(((nb * 64 + row) * VST + cv) * 4),
                     vb + (size_t)row * Cc + cv);
            }
            CP_COMMIT();
            CP_WAIT1();
        } else {
            CP_WAIT0();
        }
        __syncthreads();

        const int k0 = kt * 64;
        if (k0 <= q0 + wq0 + 31) {      // warp tile not fully masked
            const __half* Ks = Ksm + buf * 64 * KSTH;
            const uint32_t* Vs = (const uint32_t*)(Vsm + buf * 64 * VST);

            // ---- S = Q@K^T (fp16 mma, K frags shared by both row-groups) ----
            float s[2][8][4];
            #pragma unroll
            for (int rg = 0; rg < 2; rg++)
                #pragma unroll
                for (int j = 0; j < 8; j++)
                    #pragma unroll
                    for (int r = 0; r < 4; r++) s[rg][j][r] = 0.0f;

            #pragma unroll
            for (int ks = 0; ks < 4; ks++) {
                #pragma unroll
                for (int j = 0; j < 8; j++) {
                    uint32_t bfr[2];
                    const __half* kp = Ks + (j * 8 + gr) * KSTH + ks * 16 + gc * 2;
                    bfr[0] = *(const uint32_t*)(kp);
                    bfr[1] = *(const uint32_t*)(kp + 8);
                    mma_f16(s[0][j], qf[0][ks], bfr);
                    mma_f16(s[1][j], qf[1][ks], bfr);
                }
            }
            // scale (exact pow2), applied post-mma
            #pragma unroll
            for (int rg = 0; rg < 2; rg++)
                #pragma unroll
                for (int j = 0; j < 8; j++)
                    #pragma unroll
                    for (int r = 0; r < 4; r++) s[rg][j][r] *= 0.125f;

            // ---- per row-group: mask, softmax, P store ----
            #pragma unroll
            for (int rg = 0; rg < 2; rg++) {
                const int rb = q0 + wq0 + rg * 16;
                if (k0 + 63 > rb) {
                    const int rlo = rb + gr, rhi = rlo + 8;
                    #pragma unroll
                    for (int j = 0; j < 8; j++) {
                        const int col = k0 + j * 8 + gc * 2;
                        if (col     > rlo) s[rg][j][0] = -1e30f;
                        if (col + 1 > rlo) s[rg][j][1] = -1e30f;
                        if (col     > rhi) s[rg][j][2] = -1e30f;
                        if (col + 1 > rhi) s[rg][j][3] = -1e30f;
                    }
                }

                float mx_lo = -1e30f, mx_hi = -1e30f;
                #pragma unroll
                for (int j = 0; j < 8; j++) {
                    mx_lo = fmaxf(mx_lo, fmaxf(s[rg][j][0], s[rg][j][1]));
                    mx_hi = fmaxf(mx_hi, fmaxf(s[rg][j][2], s[rg][j][3]));
                }
                mx_lo = fmaxf(mx_lo, __shfl_xor_sync(0xffffffffu, mx_lo, 1));
                mx_lo = fmaxf(mx_lo, __shfl_xor_sync(0xffffffffu, mx_lo, 2));
                mx_hi = fmaxf(mx_hi, __shfl_xor_sync(0xffffffffu, mx_hi, 1));
                mx_hi = fmaxf(mx_hi, __shfl_xor_sync(0xffffffffu, mx_hi, 2));

                const float nm_lo = fmaxf(m_lo[rg], mx_lo);
                const float nm_hi = fmaxf(m_hi[rg], mx_hi);
                const float al_lo = __expf(m_lo[rg] - nm_lo);
                const float al_hi = __expf(m_hi[rg] - nm_hi);
                m_lo[rg] = nm_lo; m_hi[rg] = nm_hi;

                float sm_lo = 0.0f, sm_hi = 0.0f;
                #pragma unroll
                for (int j = 0; j < 8; j++) {
                    s[rg][j][0] = __expf(s[rg][j][0] - nm_lo);
                    s[rg][j][1] = __expf(s[rg][j][1] - nm_lo);
                    s[rg][j][2] = __expf(s[rg][j][2] - nm_hi);
                    s[rg][j][3] = __expf(s[rg][j][3] - nm_hi);
                    sm_lo += s[rg][j][0] + s[rg][j][1];
                    sm_hi += s[rg][j][2] + s[rg][j][3];
                }
                sm_lo += __shfl_xor_sync(0xffffffffu, sm_lo, 1);
                sm_lo += __shfl_xor_sync(0xffffffffu, sm_lo, 2);
                sm_hi += __shfl_xor_sync(0xffffffffu, sm_hi, 1);
                sm_hi += __shfl_xor_sync(0xffffffffu, sm_hi, 2);
                l_lo[rg] = l_lo[rg] * al_lo + sm_lo;
                l_hi[rg] = l_hi[rg] * al_hi + sm_hi;

                #pragma unroll
                for (int j = 0; j < 8; j++) {
                    o[rg][j][0] *= al_lo; o[rg][j][1] *= al_lo;
                    o[rg][j][2] *= al_hi; o[rg][j][3] *= al_hi;
                }

                uint32_t* pp = (uint32_t*)Psm + (wq0 + rg * 16 + gr) * PST + gc * 2;
                #pragma unroll
                for (int j = 0; j < 8; j++) {
                    uint2 v0 = { f2tf32(s[rg][j][0]), f2tf32(s[rg][j][1]) };
                    uint2 v1 = { f2tf32(s[rg][j][2]), f2tf32(s[rg][j][3]) };
                    *(uint2*)(pp + j * 8)           = v0;
                    *(uint2*)(pp + j * 8 + 8 * PST) = v1;
                }
            }
            __syncwarp();

            // ---- O += P @ V (tf32 mma, V frags shared by both row-groups) ----
            #pragma unroll
            for (int kk = 0; kk < 8; kk++) {
                uint32_t pf[2][4];
                #pragma unroll
                for (int rg = 0; rg < 2; rg++) {
                    const uint32_t* pq = (const uint32_t*)Psm +
                                         (wq0 + rg * 16 + gr) * PST + kk * 8 + gc;
                    pf[rg][0] = pq[0];
                    pf[rg][1] = pq[8 * PST];
                    pf[rg][2] = pq[4];
                    pf[rg][3] = pq[8 * PST + 4];
                }
                #pragma unroll
                for (int j2 = 0; j2 < 8; j2++) {
                    uint32_t vf[2];
                    const uint32_t* vp = Vs + (kk * 8 + gc) * VST + j2 * 8 + gr;
                    vf[0] = vp[0];
                    vf[1] = vp[4 * VST];
                    mma_tf32(o[0][j2], pf[0], vf);
                    mma_tf32(o[1][j2], pf[1], vf);
                }
            }
            __syncwarp();
        }
        __syncthreads();
        buf ^= 1;
    }

    // ---- normalize + write half ----
    #pragma unroll
    for (int rg = 0; rg < 2; rg++) {
        const float il_lo = 1.0f / l_lo[rg];
        const float il_hi = 1.0f / l_hi[rg];
        __half* olo = outp + (size_t)(b * Tn + q0 + wq0 + rg * 16 + gr) * Cc
                           + h * HD + gc * 2;
        __half* ohi = olo + (size_t)8 * Cc;
        #pragma unroll
        for (int j2 = 0; j2 < 8; j2++) {
            __half2 h0 = __floats2half2_rn(o[rg][j2][0] * il_lo, o[rg][j2][1] * il_lo);
            __half2 h1 = __floats2half2_rn(o[rg][j2][2] * il_hi, o[rg][j2][3] * il_hi);
            *(__half2*)(olo + j2 * 8) = h0;
            *(__half2*)(ohi + j2 * 8) = h1;
        }
    }
}

// ===========================================================================
// Launch
// ===========================================================================
extern "C" void kernel_launch(void* const* d_in, const int* in_sizes, int n_in,
                              void* d_out, int out_size)
{
    const float* x      = (const float*)d_in[0];   // (B,T,C)
    const float* w_attn = (const float*)d_in[1];   // (3C, C)
    const float* w_proj = (const float*)d_in[2];   // (C, C)
    float* out = (float*)d_out;                    // (B,T,C)

    __half *xh_p, *wah_p, *wph_p, *qkh_p, *ath_p;
    float *v_p;
    cudaGetSymbolAddress((void**)&xh_p,  g_xh);
    cudaGetSymbolAddress((void**)&wah_p, g_wah);
    cudaGetSymbolAddress((void**)&wph_p, g_wph);
    cudaGetSymbolAddress((void**)&qkh_p, g_qkh);
    cudaGetSymbolAddress((void**)&v_p,   g_v);
    cudaGetSymbolAddress((void**)&ath_p, g_ath);

    cudaFuncSetAttribute(gemm_f16_kernel<0>,
                         cudaFuncAttributeMaxDynamicSharedMemorySize, GEMM_SMEM);
    cudaFuncSetAttribute(gemm_f16_kernel<1>,
                         cudaFuncAttributeMaxDynamicSharedMemorySize, GEMM_SMEM);
    cudaFuncSetAttribute(flash_tc_kernel,
                         cudaFuncAttributeMaxDynamicSharedMemorySize, FLASH_SMEM);

    // 0) convert inputs to half
    to_half_kernel<<<MTOT * Cc / 8 / 256, 256>>>((const float4*)x, (uint4*)xh_p,
                                                 MTOT * Cc / 8);
    to_half_kernel<<<3 * Cc * Cc / 8 / 256, 256>>>((const float4*)w_attn,
                                                   (uint4*)wah_p, 3 * Cc * Cc / 8);
    to_half_kernel<<<Cc * Cc / 8 / 256, 256>>>((const float4*)w_proj,
                                               (uint4*)wph_p, Cc * Cc / 8);

    // 1) QKV = x @ w_attn^T : M=8192, N=3072, K=1024 -> qk half + v f32
    {
        dim3 grid(3 * Cc / 128, MTOT / 128);
        gemm_f16_kernel<1><<<grid, 256, GEMM_SMEM>>>(
            xh_p, wah_p, nullptr, qkh_p, v_p, 3 * Cc, Cc);
    }

    // 2) Flash attention -> att half
    {
        dim3 grid(Tn / QROWS, Bn * NH);
        flash_tc_kernel<<<grid, 128, FLASH_SMEM>>>(qkh_p, v_p, ath_p);
    }

    // 3) out = att @ w_proj^T : M=8192, N=1024, K=1024 (f32 out)
    {
        dim3 grid(Cc / 128, MTOT / 128);
        gemm_f16_kernel<0><<<grid, 256, GEMM_SMEM>>>(
            ath_p, wph_p, out, nullptr, nullptr, Cc, Cc);
    }
}

// round 12
// speedup vs baseline: 2.1041x; 1.2860x over previous
#include <cuda_runtime.h>
#include <cuda_fp16.h>
#include <math.h>
#include <stdint.h>

// Problem constants (B=4, T=2048, C=1024, H=16, D=64)
#define Bn   4
#define Tn   2048
#define Cc   1024
#define NH   16
#define HD   64
#define MTOT (Bn * Tn)          // 8192 rows

// Scratch (device globals: allocation is forbidden)
__device__ __half g_xh [(size_t)MTOT * Cc];        // x (half)
__device__ __half g_wah[(size_t)3 * Cc * Cc];      // w_attn (half)
__device__ __half g_wph[(size_t)Cc * Cc];          // w_proj (half)
__device__ __half g_qkv[(size_t)MTOT * 3 * Cc];    // qkv (half), (B*T, 3C)
__device__ __half g_ath[(size_t)MTOT * Cc];        // attention out (half)

// ===========================================================================
// Helpers
// ===========================================================================
__device__ __forceinline__ uint32_t smem_u32(const void* p) {
    uint32_t a;
    asm("{ .reg .u64 t; cvta.to.shared.u64 t, %1; cvt.u32.u64 %0, t; }"
        : "=r"(a) : "l"(p));
    return a;
}
__device__ __forceinline__ uint32_t packh2(float a, float b) {
    __half2 h = __floats2half2_rn(a, b);
    return *(uint32_t*)&h;
}
// fp16 mma: D(16x8,f32) = A(16x16,f16,row) @ B(16x8,f16,col) + D
__device__ __forceinline__ void mma_f16(float* c, const uint32_t* a, const uint32_t* b) {
    asm volatile(
        "mma.sync.aligned.m16n8k16.row.col.f32.f16.f16.f32 "
        "{%0,%1,%2,%3}, {%4,%5,%6,%7}, {%8,%9}, {%0,%1,%2,%3};"
        : "+f"(c[0]), "+f"(c[1]), "+f"(c[2]), "+f"(c[3])
        : "r"(a[0]), "r"(a[1]), "r"(a[2]), "r"(a[3]), "r"(b[0]), "r"(b[1]));
}
#define LDMX4(r0,r1,r2,r3,addr) \
    asm volatile("ldmatrix.sync.aligned.m8n8.x4.shared.b16 {%0,%1,%2,%3}, [%4];" \
        : "=r"(r0), "=r"(r1), "=r"(r2), "=r"(r3) : "r"(addr))
#define LDMX4T(r0,r1,r2,r3,addr) \
    asm volatile("ldmatrix.sync.aligned.m8n8.x4.trans.shared.b16 {%0,%1,%2,%3}, [%4];" \
        : "=r"(r0), "=r"(r1), "=r"(r2), "=r"(r3) : "r"(addr))
#define CP16(smem, gmem) \
    asm volatile("cp.async.cg.shared.global [%0], [%1], 16;" \
                 :: "r"(smem), "l"(gmem) : "memory")
#define CP_COMMIT() asm volatile("cp.async.commit_group;" ::: "memory")
#define CP_WAIT0()  asm volatile("cp.async.wait_group 0;" ::: "memory")
#define CP_WAIT1()  asm volatile("cp.async.wait_group 1;" ::: "memory")
#define CP_WAIT2()  asm volatile("cp.async.wait_group 2;" ::: "memory")

// ===========================================================================
// Convert pass: fp32 -> fp16 (8 elems / thread, 16B stores)
// ===========================================================================
__global__ __launch_bounds__(256) void to_half_kernel(
    const float4* __restrict__ in, uint4* __restrict__ out, int n8)
{
    int i = blockIdx.x * blockDim.x + threadIdx.x;
    if (i < n8) {
        float4 a = in[2 * i], b = in[2 * i + 1];
        uint4 o = { packh2(a.x, a.y), packh2(a.z, a.w),
                    packh2(b.x, b.y), packh2(b.z, b.w) };
        out[i] = o;
    }
}

// ===========================================================================
// FP16 GEMM: C[M,N] = A[M,K] @ B[N,K]^T, half K-major in, f32 acc.
// CTA 128x128, BK=32, 256 thr (8 warps 2x4, 64x32/warp), 3-stage cp.async.
// Fragments via ldmatrix.x4 (stride 40 halves = 5x16B chunks: conflict-free).
// MODE 0: C f32 (stride N).  MODE 1: out half (stride N) -> qkv.
// ===========================================================================
#define GH_ST  40
#define HTILE  (128 * GH_ST)
#define HSTAGE (2 * HTILE)
#define GEMM_SMEM (3 * HSTAGE * 2)            // 61440 B

template <int MODE>
__global__ __launch_bounds__(256, 2) void gemm_f16_kernel(
    const __half* __restrict__ A, const __half* __restrict__ B,
    float* __restrict__ C, __half* __restrict__ HC, int N, int K)
{
    extern __shared__ char smc[];
    __half* sg = (__half*)smc;
    const uint32_t sb = smem_u32(sg);
    const int tid = threadIdx.x;
    const int wid = tid >> 5, lane = tid & 31;
    const int gr = lane >> 2, gc = lane & 3;
    const int m0 = blockIdx.y * 128, n0 = blockIdx.x * 128;
    const int wm0 = (wid >> 2) * 64, wn0 = (wid & 3) * 32;

    // ldmatrix lane geometry
    const uint32_t arow = (lane & 7) + ((lane >> 3) & 1) * 8;
    const uint32_t acol = (lane >> 4) * 8;
    const uint32_t brow = (lane & 7) + (lane >> 4) * 8;
    const uint32_t bcol = ((lane >> 3) & 1) * 8;

    float acc[4][4][4];
    #pragma unroll
    for (int i = 0; i < 4; i++)
        #pragma unroll
        for (int j = 0; j < 4; j++)
            #pragma unroll
            for (int r = 0; r < 4; r++) acc[i][j][r] = 0.0f;

    const int r0 = tid >> 2;            // 0..63
    const int c8 = (tid & 3) * 8;       // halves
    const __half* Ag = A + (size_t)(m0 + r0) * K + c8;
    const __half* Bg = B + (size_t)(n0 + r0) * K + c8;
    const size_t rowstep = (size_t)64 * K;
    const int KCH = K / 32;

    #pragma unroll
    for (int s = 0; s < 2; s++) {
        const uint32_t st = sb + (uint32_t)(s * HSTAGE * 2);
        #pragma unroll
        for (int it = 0; it < 2; it++) {
            uint32_t off = (uint32_t)(((r0 + it * 64) * GH_ST + c8) * 2);
            CP16(st + off,             Ag + it * rowstep + s * 32);
            CP16(st + off + HTILE * 2, Bg + it * rowstep + s * 32);
        }
        CP_COMMIT();
    }

    for (int c = 0; c < KCH; c++) {
        if (c + 2 < KCH) {
            const uint32_t st = sb + (uint32_t)(((c + 2) % 3) * HSTAGE * 2);
            #pragma unroll
            for (int it = 0; it < 2; it++) {
                uint32_t off = (uint32_t)(((r0 + it * 64) * GH_ST + c8) * 2);
                CP16(st + off,             Ag + it * rowstep + (c + 2) * 32);
                CP16(st + off + HTILE * 2, Bg + it * rowstep + (c + 2) * 32);
            }
            CP_COMMIT();
            CP_WAIT2();
        } else if (c + 1 < KCH) {
            CP_WAIT1();
        } else {
            CP_WAIT0();
        }
        __syncthreads();

        const uint32_t sA = sb + (uint32_t)((c % 3) * HSTAGE * 2);
        const uint32_t sB = sA + (uint32_t)(HTILE * 2);
        #pragma unroll
        for (int ks = 0; ks < 2; ks++) {
            uint32_t af[4][4], bf[4][2];
            #pragma unroll
            for (int i = 0; i < 4; i++)
                LDMX4(af[i][0], af[i][1], af[i][2], af[i][3],
                      sA + (uint32_t)((((wm0 + i * 16 + arow) * GH_ST) +
                                       ks * 16 + acol) * 2));
            #pragma unroll
            for (int jp = 0; jp < 2; jp++) {
                uint32_t b0, b1, b2, b3;
                LDMX4(b0, b1, b2, b3,
                      sB + (uint32_t)((((wn0 + jp * 16 + brow) * GH_ST) +
                                       ks * 16 + bcol) * 2));
                bf[2 * jp][0] = b0; bf[2 * jp][1] = b1;
                bf[2 * jp + 1][0] = b2; bf[2 * jp + 1][1] = b3;
            }
            #pragma unroll
            for (int i = 0; i < 4; i++)
                #pragma unroll
                for (int j = 0; j < 4; j++)
                    mma_f16(acc[i][j], af[i], bf[j]);
        }
        __syncthreads();
    }

    #pragma unroll
    for (int i = 0; i < 4; i++)
        #pragma unroll
        for (int j = 0; j < 4; j++) {
            const int row = m0 + wm0 + i * 16 + gr;
            const int col = n0 + wn0 + j * 8 + gc * 2;
            if (MODE == 0) {
                float* cr = C + (size_t)row * N + col;
                float2 v0 = { acc[i][j][0], acc[i][j][1] };
                float2 v1 = { acc[i][j][2], acc[i][j][3] };
                *(float2*)cr           = v0;
                *(float2*)(cr + 8 * N) = v1;
            } else {
                __half* hr = HC + (size_t)row * N + col;
                *(__half2*)hr                     = __floats2half2_rn(acc[i][j][0], acc[i][j][1]);
                *(__half2*)(hr + (size_t)8 * N)   = __floats2half2_rn(acc[i][j][2], acc[i][j][3]);
            }
        }
}

// ===========================================================================
// Flash attention (causal), all-fp16 mma, f32 accum/softmax.
// CTA: 128 thr (4 warps), q-tile 128 (warp owns 32 rows = 2 row-groups of 16),
// k-tile 64, D=64. Q in regs; K frags via ldmatrix; V frags via ldmatrix.trans;
// P stays IN REGISTERS (S C-fragment == P A-fragment after half2 packing).
// ===========================================================================
#define KSTH 72                 // halves: 144B row = 9x16B -> ldmatrix conflict-free
#define VSTH 72
#define QROWS 128
#define FLASH_SMEM ((2 * 64 * KSTH + 2 * 64 * VSTH) * 2)   // 36864 B

__global__ __launch_bounds__(128, 2) void flash_tc_kernel(
    const __half* __restrict__ qkv, __half* __restrict__ outp)
{
    extern __shared__ char smc[];
    __half* Ksm = (__half*)smc;                   // [2][64*KSTH]
    __half* Vsm = Ksm + 2 * 64 * KSTH;            // [2][64*VSTH]
    const uint32_t sbK = smem_u32(Ksm);
    const uint32_t sbV = smem_u32(Vsm);

    const int tid = threadIdx.x;
    const int wid = tid >> 5, lane = tid & 31;
    const int gr = lane >> 2, gc = lane & 3;
    const int qt = gridDim.x - 1 - blockIdx.x;    // heavy tiles first
    const int b  = blockIdx.y >> 4;
    const int h  = blockIdx.y & 15;
    const int q0 = qt * QROWS;
    const int wq0 = wid * 32;
    const size_t rst = 3 * Cc;                    // halves per qkv row

    // ldmatrix lane geometry
    const uint32_t krow = (lane & 7) + (lane >> 4) * 8;   // K: token-row within 16
    const uint32_t kcol = ((lane >> 3) & 1) * 8;          // K: k-offset
    const uint32_t vrow = lane & 15;                      // V: token-row within 16
    const uint32_t vcol = (lane >> 4) * 8;                // V: d-offset

    // ---- Q fragments: 2 row-groups x 4 k16-steps x 4 regs ----
    uint32_t qf[2][4][4];
    #pragma unroll
    for (int rg = 0; rg < 2; rg++) {
        const __half* qlo = qkv + (size_t)(b * Tn + q0 + wq0 + rg * 16 + gr) * rst
                                + h * HD;
        const __half* qhi = qlo + 8 * rst;
        #pragma unroll
        for (int ks = 0; ks < 4; ks++) {
            qf[rg][ks][0] = *(const uint32_t*)(qlo + ks * 16 + gc * 2);
            qf[rg][ks][1] = *(const uint32_t*)(qhi + ks * 16 + gc * 2);
            qf[rg][ks][2] = *(const uint32_t*)(qlo + ks * 16 + gc * 2 + 8);
            qf[rg][ks][3] = *(const uint32_t*)(qhi + ks * 16 + gc * 2 + 8);
        }
    }

    float o[2][8][4];
    #pragma unroll
    for (int rg = 0; rg < 2; rg++)
        #pragma unroll
        for (int j = 0; j < 8; j++)
            #pragma unroll
            for (int r = 0; r < 4; r++) o[rg][j][r] = 0.0f;
    float m_lo[2] = {-1e30f, -1e30f}, m_hi[2] = {-1e30f, -1e30f};
    float l_lo[2] = {0.0f, 0.0f},     l_hi[2] = {0.0f, 0.0f};

    // K/V loaders: rows rl+16*it (it<4), 8 halves each
    const int rl = tid >> 3;            // 0..15
    const int cl = (tid & 7) * 8;       // halves
    const __half* kb0 = qkv + (size_t)(b * Tn) * rst + Cc + h * HD;
    const __half* vb0 = qkv + (size_t)(b * Tn) * rst + 2 * Cc + h * HD;

    #pragma unroll
    for (int it = 0; it < 4; it++) {
        const int row = rl + it * 16;
        CP16(sbK + (uint32_t)((row * KSTH + cl) * 2), kb0 + (size_t)row * rst + cl);
        CP16(sbV + (uint32_t)((row * VSTH + cl) * 2), vb0 + (size_t)row * rst + cl);
    }
    CP_COMMIT();

    const float SC = 0.125f * 1.4426950408889634f;   // scale * log2(e)
    const int last = 2 * qt + 1;
    int buf = 0;
    for (int kt = 0; kt <= last; kt++) {
        if (kt < last) {
            const int nb = buf ^ 1;
            const __half* kb = kb0 + (size_t)(kt + 1) * 64 * rst;
            const __half* vb = vb0 + (size_t)(kt + 1) * 64 * rst;
            #pragma unroll
            for (int it = 0; it < 4; it++) {
                const int row = rl + it * 16;
                CP16(sbK + (uint32_t)(((nb * 64 + row) * KSTH + cl) * 2),
                     kb + (size_t)row * rst + cl);
                CP16(sbV + (uint32_t)(((nb * 64 + row) * VSTH + cl) * 2),
                     vb + (size_t)row * rst + cl);
            }
            CP_COMMIT();
            CP_WAIT1();
        } else {
            CP_WAIT0();
        }
        __syncthreads();

        const int k0 = kt * 64;
        if (k0 <= q0 + wq0 + 31) {      // warp tile not fully masked
            const uint32_t kbase = sbK + (uint32_t)(buf * 64 * KSTH * 2);
            const uint32_t vbase = sbV + (uint32_t)(buf * 64 * VSTH * 2);

            // ---- S = Q@K^T (K frags via ldmatrix, shared by row-groups) ----
            float s[2][8][4];
            #pragma unroll
            for (int rg = 0; rg < 2; rg++)
                #pragma unroll
                for (int j = 0; j < 8; j++)
                    #pragma unroll
                    for (int r = 0; r < 4; r++) s[rg][j][r] = 0.0f;

            #pragma unroll
            for (int ks = 0; ks < 4; ks++) {
                #pragma unroll
                for (int jp = 0; jp < 4; jp++) {
                    uint32_t b0, b1, b2, b3;
                    LDMX4(b0, b1, b2, b3,
                          kbase + (uint32_t)((((jp * 16 + krow) * KSTH) +
                                              ks * 16 + kcol) * 2));
                    uint32_t bf0[2] = { b0, b1 }, bf1[2] = { b2, b3 };
                    mma_f16(s[0][2 * jp],     qf[0][ks], bf0);
                    mma_f16(s[0][2 * jp + 1], qf[0][ks], bf1);
                    mma_f16(s[1][2 * jp],     qf[1][ks], bf0);
                    mma_f16(s[1][2 * jp + 1], qf[1][ks], bf1);
                }
            }

            // ---- scale into log2 domain + causal mask ----
            #pragma unroll
            for (int rg = 0; rg < 2; rg++)
                #pragma unroll
                for (int j = 0; j < 8; j++)
                    #pragma unroll
                    for (int r = 0; r < 4; r++) s[rg][j][r] *= SC;

            #pragma unroll
            for (int rg = 0; rg < 2; rg++) {
                const int rb = q0 + wq0 + rg * 16;
                if (k0 + 63 > rb) {
                    const int rlo = rb + gr, rhi = rlo + 8;
                    #pragma unroll
                    for (int j = 0; j < 8; j++) {
                        const int col = k0 + j * 8 + gc * 2;
                        if (col     > rlo) s[rg][j][0] = -1e30f;
                        if (col + 1 > rlo) s[rg][j][1] = -1e30f;
                        if (col     > rhi) s[rg][j][2] = -1e30f;
                        if (col + 1 > rhi) s[rg][j][3] = -1e30f;
                    }
                }

                // ---- online softmax (base-2) ----
                float mx_lo = -1e30f, mx_hi = -1e30f;
                #pragma unroll
                for (int j = 0; j < 8; j++) {
                    mx_lo = fmaxf(mx_lo, fmaxf(s[rg][j][0], s[rg][j][1]));
                    mx_hi = fmaxf(mx_hi, fmaxf(s[rg][j][2], s[rg][j][3]));
                }
                mx_lo = fmaxf(mx_lo, __shfl_xor_sync(0xffffffffu, mx_lo, 1));
                mx_lo = fmaxf(mx_lo, __shfl_xor_sync(0xffffffffu, mx_lo, 2));
                mx_hi = fmaxf(mx_hi, __shfl_xor_sync(0xffffffffu, mx_hi, 1));
                mx_hi = fmaxf(mx_hi, __shfl_xor_sync(0xffffffffu, mx_hi, 2));

                const float nm_lo = fmaxf(m_lo[rg], mx_lo);
                const float nm_hi = fmaxf(m_hi[rg], mx_hi);
                const float al_lo = exp2f(m_lo[rg] - nm_lo);
                const float al_hi = exp2f(m_hi[rg] - nm_hi);
                m_lo[rg] = nm_lo; m_hi[rg] = nm_hi;

                float sm_lo = 0.0f, sm_hi = 0.0f;
                #pragma unroll
                for (int j = 0; j < 8; j++) {
                    s[rg][j][0] = exp2f(s[rg][j][0] - nm_lo);
                    s[rg][j][1] = exp2f(s[rg][j][1] - nm_lo);
                    s[rg][j][2] = exp2f(s[rg][j][2] - nm_hi);
                    s[rg][j][3] = exp2f(s[rg][j][3] - nm_hi);
                    sm_lo += s[rg][j][0] + s[rg][j][1];
                    sm_hi += s[rg][j][2] + s[rg][j][3];
                }
                sm_lo += __shfl_xor_sync(0xffffffffu, sm_lo, 1);
                sm_lo += __shfl_xor_sync(0xffffffffu, sm_lo, 2);
                sm_hi += __shfl_xor_sync(0xffffffffu, sm_hi, 1);
                sm_hi += __shfl_xor_sync(0xffffffffu, sm_hi, 2);
                l_lo[rg] = l_lo[rg] * al_lo + sm_lo;
                l_hi[rg] = l_hi[rg] * al_hi + sm_hi;

                #pragma unroll
                for (int j = 0; j < 8; j++) {
                    o[rg][j][0] *= al_lo; o[rg][j][1] *= al_lo;
                    o[rg][j][2] *= al_hi; o[rg][j][3] *= al_hi;
                }
            }

            // ---- O += P @ V : P in registers (C-frag == A-frag after pack),
            //      V frags via ldmatrix.trans, shared by row-groups ----
            #pragma unroll
            for (int kk = 0; kk < 4; kk++) {            // k16 blocks
                uint32_t pf0[4], pf1[4];
                pf0[0] = packh2(s[0][2 * kk][0],     s[0][2 * kk][1]);
                pf0[1] = packh2(s[0][2 * kk][2],     s[0][2 * kk][3]);
                pf0[2] = packh2(s[0][2 * kk + 1][0], s[0][2 * kk + 1][1]);
                pf0[3] = packh2(s[0][2 * kk + 1][2], s[0][2 * kk + 1][3]);
                pf1[0] = packh2(s[1][2 * kk][0],     s[1][2 * kk][1]);
                pf1[1] = packh2(s[1][2 * kk][2],     s[1][2 * kk][3]);
                pf1[2] = packh2(s[1][2 * kk + 1][0], s[1][2 * kk + 1][1]);
                pf1[3] = packh2(s[1][2 * kk + 1][2], s[1][2 * kk + 1][3]);
                #pragma unroll
                for (int nb = 0; nb < 4; nb++) {        // n16 blocks
                    uint32_t b0, b1, b2, b3;
                    LDMX4T(b0, b1, b2, b3,
                           vbase + (uint32_t)((((kk * 16 + vrow) * VSTH) +
                                               nb * 16 + vcol) * 2));
                    uint32_t bf0[2] = { b0, b1 }, bf1[2] = { b2, b3 };
                    mma_f16(o[0][2 * nb],     pf0, bf0);
                    mma_f16(o[0][2 * nb + 1], pf0, bf1);
                    mma_f16(o[1][2 * nb],     pf1, bf0);
                    mma_f16(o[1][2 * nb + 1], pf1, bf1);
                }
            }
        }
        __syncthreads();        // K/V buffer reads done before overwrite
        buf ^= 1;
    }

    // ---- normalize + write half ----
    #pragma unroll
    for (int rg = 0; rg < 2; rg++) {
        const float il_lo = 1.0f / l_lo[rg];
        const float il_hi = 1.0f / l_hi[rg];
        __half* olo = outp + (size_t)(b * Tn + q0 + wq0 + rg * 16 + gr) * Cc
                           + h * HD + gc * 2;
        __half* ohi = olo + (size_t)8 * Cc;
        #pragma unroll
        for (int j2 = 0; j2 < 8; j2++) {
            *(__half2*)(olo + j2 * 8) =
                __floats2half2_rn(o[rg][j2][0] * il_lo, o[rg][j2][1] * il_lo);
            *(__half2*)(ohi + j2 * 8) =
                __floats2half2_rn(o[rg][j2][2] * il_hi, o[rg][j2][3] * il_hi);
        }
    }
}

// ===========================================================================
// Launch
// ===========================================================================
extern "C" void kernel_launch(void* const* d_in, const int* in_sizes, int n_in,
                              void* d_out, int out_size)
{
    const float* x      = (const float*)d_in[0];   // (B,T,C)
    const float* w_attn = (const float*)d_in[1];   // (3C, C)
    const float* w_proj = (const float*)d_in[2];   // (C, C)
    float* out = (float*)d_out;                    // (B,T,C)

    __half *xh_p, *wah_p, *wph_p, *qkv_p, *ath_p;
    cudaGetSymbolAddress((void**)&xh_p,  g_xh);
    cudaGetSymbolAddress((void**)&wah_p, g_wah);
    cudaGetSymbolAddress((void**)&wph_p, g_wph);
    cudaGetSymbolAddress((void**)&qkv_p, g_qkv);
    cudaGetSymbolAddress((void**)&ath_p, g_ath);

    cudaFuncSetAttribute(gemm_f16_kernel<0>,
                         cudaFuncAttributeMaxDynamicSharedMemorySize, GEMM_SMEM);
    cudaFuncSetAttribute(gemm_f16_kernel<1>,
                         cudaFuncAttributeMaxDynamicSharedMemorySize, GEMM_SMEM);
    cudaFuncSetAttribute(flash_tc_kernel,
                         cudaFuncAttributeMaxDynamicSharedMemorySize, FLASH_SMEM);

    // 0) convert inputs to half
    to_half_kernel<<<MTOT * Cc / 8 / 256, 256>>>((const float4*)x, (uint4*)xh_p,
                                                 MTOT * Cc / 8);
    to_half_kernel<<<3 * Cc * Cc / 8 / 256, 256>>>((const float4*)w_attn,
                                                   (uint4*)wah_p, 3 * Cc * Cc / 8);
    to_half_kernel<<<Cc * Cc / 8 / 256, 256>>>((const float4*)w_proj,
                                               (uint4*)wph_p, Cc * Cc / 8);

    // 1) QKV = x @ w_attn^T : M=8192, N=3072, K=1024 -> half
    {
        dim3 grid(3 * Cc / 128, MTOT / 128);
        gemm_f16_kernel<1><<<grid, 256, GEMM_SMEM>>>(
            xh_p, wah_p, nullptr, qkv_p, 3 * Cc, Cc);
    }

    // 2) Flash attention -> att half
    {
        dim3 grid(Tn / QROWS, Bn * NH);
        flash_tc_kernel<<<grid, 128, FLASH_SMEM>>>(qkv_p, ath_p);
    }

    // 3) out = att @ w_proj^T : M=8192, N=1024, K=1024 (f32 out)
    {
        dim3 grid(Cc / 128, MTOT / 128);
        gemm_f16_kernel<0><<<grid, 256, GEMM_SMEM>>>(
            ath_p, wph_p, out, nullptr, Cc, Cc);
    }
}

// round 13
// speedup vs baseline: 2.1968x; 1.0441x over previous
#include <cuda_runtime.h>
#include <cuda_fp16.h>
#include <math.h>
#include <stdint.h>

// Problem constants (B=4, T=2048, C=1024, H=16, D=64)
#define Bn   4
#define Tn   2048
#define Cc   1024
#define NH   16
#define HD   64
#define MTOT (Bn * Tn)          // 8192 rows

// Scratch (device globals: allocation is forbidden)
__device__ __half g_xh [(size_t)MTOT * Cc];        // x (half)
__device__ __half g_wah[(size_t)3 * Cc * Cc];      // w_attn (half)
__device__ __half g_wph[(size_t)Cc * Cc];          // w_proj (half)
__device__ __half g_qkv[(size_t)MTOT * 3 * Cc];    // qkv (half), (B*T, 3C)
__device__ __half g_ath[(size_t)MTOT * Cc];        // attention out (half)

// ===========================================================================
// Helpers
// ===========================================================================
__device__ __forceinline__ uint32_t smem_u32(const void* p) {
    uint32_t a;
    asm("{ .reg .u64 t; cvta.to.shared.u64 t, %1; cvt.u32.u64 %0, t; }"
        : "=r"(a) : "l"(p));
    return a;
}
__device__ __forceinline__ uint32_t packh2(float a, float b) {
    __half2 h = __floats2half2_rn(a, b);
    return *(uint32_t*)&h;
}
// fp16 mma: D(16x8,f32) = A(16x16,f16,row) @ B(16x8,f16,col) + D
__device__ __forceinline__ void mma_f16(float* c, const uint32_t* a, const uint32_t* b) {
    asm volatile(
        "mma.sync.aligned.m16n8k16.row.col.f32.f16.f16.f32 "
        "{%0,%1,%2,%3}, {%4,%5,%6,%7}, {%8,%9}, {%0,%1,%2,%3};"
        : "+f"(c[0]), "+f"(c[1]), "+f"(c[2]), "+f"(c[3])
        : "r"(a[0]), "r"(a[1]), "r"(a[2]), "r"(a[3]), "r"(b[0]), "r"(b[1]));
}
#define LDMX4(r0,r1,r2,r3,addr) \
    asm volatile("ldmatrix.sync.aligned.m8n8.x4.shared.b16 {%0,%1,%2,%3}, [%4];" \
        : "=r"(r0), "=r"(r1), "=r"(r2), "=r"(r3) : "r"(addr))
#define LDMX4T(r0,r1,r2,r3,addr) \
    asm volatile("ldmatrix.sync.aligned.m8n8.x4.trans.shared.b16 {%0,%1,%2,%3}, [%4];" \
        : "=r"(r0), "=r"(r1), "=r"(r2), "=r"(r3) : "r"(addr))
#define CP16(smem, gmem) \
    asm volatile("cp.async.cg.shared.global [%0], [%1], 16;" \
                 :: "r"(smem), "l"(gmem) : "memory")
#define CP_COMMIT() asm volatile("cp.async.commit_group;" ::: "memory")
#define CP_WAIT0()  asm volatile("cp.async.wait_group 0;" ::: "memory")
#define CP_WAIT1()  asm volatile("cp.async.wait_group 1;" ::: "memory")

// ===========================================================================
// Convert pass: fp32 -> fp16 (8 elems / thread, 16B stores)
// ===========================================================================
__global__ __launch_bounds__(256) void to_half_kernel(
    const float4* __restrict__ in, uint4* __restrict__ out, int n8)
{
    int i = blockIdx.x * blockDim.x + threadIdx.x;
    if (i < n8) {
        float4 a = in[2 * i], b = in[2 * i + 1];
        uint4 o = { packh2(a.x, a.y), packh2(a.z, a.w),
                    packh2(b.x, b.y), packh2(b.z, b.w) };
        out[i] = o;
    }
}

// ===========================================================================
// FP16 GEMM (PERSISTENT): C[M,N] = A[M,K] @ B[N,K]^T, half K-major, f32 acc.
// CTA tile 128x128, BK=64, 2-stage cp.async, 256 thr (8 warps 2x4, 64x32/warp).
// Persistent: grid = 2*SMs CTAs loop over tiles -> no wave quantization.
// Smem stride 72 halves (144B = 9x16B): ldmatrix conflict-free (proven R12).
// MODE 0: C f32 out.  MODE 1: half out (qkv).
// ===========================================================================
#define GH_ST  72
#define HTILE  (128 * GH_ST)                  // 9216 halves per (A or B) tile
#define HSTAGE (2 * HTILE)                    // 18432 halves = 36864 B
#define GEMM_SMEM (2 * HSTAGE * 2)            // 73728 B
#define GEMM_GRID 304                         // 2 CTAs/SM x 152 SMs (GB300)

template <int MODE>
__global__ __launch_bounds__(256, 2) void gemm_f16_kernel(
    const __half* __restrict__ A, const __half* __restrict__ B,
    float* __restrict__ C, __half* __restrict__ HC, int M, int N, int K)
{
    extern __shared__ char smc[];
    const uint32_t sb = smem_u32(smc);
    const int tid = threadIdx.x;
    const int wid = tid >> 5, lane = tid & 31;
    const int gr = lane >> 2, gc = lane & 3;
    const int wm0 = (wid >> 2) * 64, wn0 = (wid & 3) * 32;

    // ldmatrix lane geometry
    const uint32_t arow = (lane & 7) + ((lane >> 3) & 1) * 8;
    const uint32_t acol = (lane >> 4) * 8;
    const uint32_t brow = (lane & 7) + (lane >> 4) * 8;
    const uint32_t bcol = ((lane >> 3) & 1) * 8;

    // loader geometry: 32 rows x 64 halves per pass, 4 passes per 128-row tile
    const int rl = tid >> 3;            // 0..31
    const int cl = (tid & 7) * 8;       // halves

    const int KCH = K / 64;
    const int NX = N / 128;
    const int ntiles = (M / 128) * NX;

    for (int t = blockIdx.x; t < ntiles; t += gridDim.x) {
        const int m0 = (t / NX) * 128, n0 = (t % NX) * 128;

        float acc[4][4][4];
        #pragma unroll
        for (int i = 0; i < 4; i++)
            #pragma unroll
            for (int j = 0; j < 4; j++)
                #pragma unroll
                for (int r = 0; r < 4; r++) acc[i][j][r] = 0.0f;

        const __half* Ag = A + (size_t)(m0 + rl) * K + cl;
        const __half* Bg = B + (size_t)(n0 + rl) * K + cl;

        // prefetch chunks 0,1
        #pragma unroll
        for (int s = 0; s < 2; s++) {
            const uint32_t st = sb + (uint32_t)(s * HSTAGE * 2);
            #pragma unroll
            for (int it = 0; it < 4; it++) {
                uint32_t off = (uint32_t)(((rl + it * 32) * GH_ST + cl) * 2);
                CP16(st + off,             Ag + (size_t)it * 32 * K + s * 64);
                CP16(st + off + HTILE * 2, Bg + (size_t)it * 32 * K + s * 64);
            }
            CP_COMMIT();
        }

        for (int c = 0; c < KCH; c++) {
            if (c + 1 < KCH) { CP_WAIT1(); } else { CP_WAIT0(); }
            __syncthreads();

            const uint32_t sA = sb + (uint32_t)((c & 1) * HSTAGE * 2);
            const uint32_t sB = sA + (uint32_t)(HTILE * 2);
            #pragma unroll
            for (int ks = 0; ks < 4; ks++) {
                uint32_t af[4][4], bf[4][2];
                #pragma unroll
                for (int i = 0; i < 4; i++)
                    LDMX4(af[i][0], af[i][1], af[i][2], af[i][3],
                          sA + (uint32_t)((((wm0 + i * 16 + arow) * GH_ST) +
                                           ks * 16 + acol) * 2));
                #pragma unroll
                for (int jp = 0; jp < 2; jp++) {
                    uint32_t b0, b1, b2, b3;
                    LDMX4(b0, b1, b2, b3,
                          sB + (uint32_t)((((wn0 + jp * 16 + brow) * GH_ST) +
                                           ks * 16 + bcol) * 2));
                    bf[2 * jp][0] = b0; bf[2 * jp][1] = b1;
                    bf[2 * jp + 1][0] = b2; bf[2 * jp + 1][1] = b3;
                }
                #pragma unroll
                for (int i = 0; i < 4; i++)
                    #pragma unroll
                    for (int j = 0; j < 4; j++)
                        mma_f16(acc[i][j], af[i], bf[j]);
            }
            __syncthreads();

            if (c + 2 < KCH) {
                const uint32_t st = sb + (uint32_t)((c & 1) * HSTAGE * 2);
                #pragma unroll
                for (int it = 0; it < 4; it++) {
                    uint32_t off = (uint32_t)(((rl + it * 32) * GH_ST + cl) * 2);
                    CP16(st + off,             Ag + (size_t)it * 32 * K + (c + 2) * 64);
                    CP16(st + off + HTILE * 2, Bg + (size_t)it * 32 * K + (c + 2) * 64);
                }
                CP_COMMIT();
            }
        }

        // epilogue
        #pragma unroll
        for (int i = 0; i < 4; i++)
            #pragma unroll
            for (int j = 0; j < 4; j++) {
                const int row = m0 + wm0 + i * 16 + gr;
                const int col = n0 + wn0 + j * 8 + gc * 2;
                if (MODE == 0) {
                    float* cr = C + (size_t)row * N + col;
                    float2 v0 = { acc[i][j][0], acc[i][j][1] };
                    float2 v1 = { acc[i][j][2], acc[i][j][3] };
                    *(float2*)cr           = v0;
                    *(float2*)(cr + 8 * N) = v1;
                } else {
                    __half* hr = HC + (size_t)row * N + col;
                    *(__half2*)hr                   = __floats2half2_rn(acc[i][j][0], acc[i][j][1]);
                    *(__half2*)(hr + (size_t)8 * N) = __floats2half2_rn(acc[i][j][2], acc[i][j][3]);
                }
            }
    }
}

// ===========================================================================
// Flash attention (causal), all-fp16 mma, f32 accum/softmax. (unchanged R12)
// CTA: 128 thr (4 warps), q-tile 128 (warp owns 32 rows = 2 row-groups of 16),
// k-tile 64, D=64. Q in regs; K/V frags via ldmatrix; P stays in registers.
// ===========================================================================
#define KSTH 72
#define VSTH 72
#define QROWS 128
#define FLASH_SMEM ((2 * 64 * KSTH + 2 * 64 * VSTH) * 2)   // 36864 B

__global__ __launch_bounds__(128, 2) void flash_tc_kernel(
    const __half* __restrict__ qkv, __half* __restrict__ outp)
{
    extern __shared__ char smc[];
    __half* Ksm = (__half*)smc;                   // [2][64*KSTH]
    __half* Vsm = Ksm + 2 * 64 * KSTH;            // [2][64*VSTH]
    const uint32_t sbK = smem_u32(Ksm);
    const uint32_t sbV = smem_u32(Vsm);

    const int tid = threadIdx.x;
    const int wid = tid >> 5, lane = tid & 31;
    const int gr = lane >> 2, gc = lane & 3;
    const int qt = gridDim.x - 1 - blockIdx.x;    // heavy tiles first
    const int b  = blockIdx.y >> 4;
    const int h  = blockIdx.y & 15;
    const int q0 = qt * QROWS;
    const int wq0 = wid * 32;
    const size_t rst = 3 * Cc;

    const uint32_t krow = (lane & 7) + (lane >> 4) * 8;
    const uint32_t kcol = ((lane >> 3) & 1) * 8;
    const uint32_t vrow = lane & 15;
    const uint32_t vcol = (lane >> 4) * 8;

    // ---- Q fragments ----
    uint32_t qf[2][4][4];
    #pragma unroll
    for (int rg = 0; rg < 2; rg++) {
        const __half* qlo = qkv + (size_t)(b * Tn + q0 + wq0 + rg * 16 + gr) * rst
                                + h * HD;
        const __half* qhi = qlo + 8 * rst;
        #pragma unroll
        for (int ks = 0; ks < 4; ks++) {
            qf[rg][ks][0] = *(const uint32_t*)(qlo + ks * 16 + gc * 2);
            qf[rg][ks][1] = *(const uint32_t*)(qhi + ks * 16 + gc * 2);
            qf[rg][ks][2] = *(const uint32_t*)(qlo + ks * 16 + gc * 2 + 8);
            qf[rg][ks][3] = *(const uint32_t*)(qhi + ks * 16 + gc * 2 + 8);
        }
    }

    float o[2][8][4];
    #pragma unroll
    for (int rg = 0; rg < 2; rg++)
        #pragma unroll
        for (int j = 0; j < 8; j++)
            #pragma unroll
            for (int r = 0; r < 4; r++) o[rg][j][r] = 0.0f;
    float m_lo[2] = {-1e30f, -1e30f}, m_hi[2] = {-1e30f, -1e30f};
    float l_lo[2] = {0.0f, 0.0f},     l_hi[2] = {0.0f, 0.0f};

    const int rl = tid >> 3;
    const int cl = (tid & 7) * 8;
    const __half* kb0 = qkv + (size_t)(b * Tn) * rst + Cc + h * HD;
    const __half* vb0 = qkv + (size_t)(b * Tn) * rst + 2 * Cc + h * HD;

    #pragma unroll
    for (int it = 0; it < 4; it++) {
        const int row = rl + it * 16;
        CP16(sbK + (uint32_t)((row * KSTH + cl) * 2), kb0 + (size_t)row * rst + cl);
        CP16(sbV + (uint32_t)((row * VSTH + cl) * 2), vb0 + (size_t)row * rst + cl);
    }
    CP_COMMIT();

    const float SC = 0.125f * 1.4426950408889634f;   // scale * log2(e)
    const int last = 2 * qt + 1;
    int buf = 0;
    for (int kt = 0; kt <= last; kt++) {
        if (kt < last) {
            const int nb = buf ^ 1;
            const __half* kb = kb0 + (size_t)(kt + 1) * 64 * rst;
            const __half* vb = vb0 + (size_t)(kt + 1) * 64 * rst;
            #pragma unroll
            for (int it = 0; it < 4; it++) {
                const int row = rl + it * 16;
                CP16(sbK + (uint32_t)(((nb * 64 + row) * KSTH + cl) * 2),
                     kb + (size_t)row * rst + cl);
                CP16(sbV + (uint32_t)(((nb * 64 + row) * VSTH + cl) * 2),
                     vb + (size_t)row * rst + cl);
            }
            CP_COMMIT();
            CP_WAIT1();
        } else {
            CP_WAIT0();
        }
        __syncthreads();

        const int k0 = kt * 64;
        if (k0 <= q0 + wq0 + 31) {
            const uint32_t kbase = sbK + (uint32_t)(buf * 64 * KSTH * 2);
            const uint32_t vbase = sbV + (uint32_t)(buf * 64 * VSTH * 2);

            float s[2][8][4];
            #pragma unroll
            for (int rg = 0; rg < 2; rg++)
                #pragma unroll
                for (int j = 0; j < 8; j++)
                    #pragma unroll
                    for (int r = 0; r < 4; r++) s[rg][j][r] = 0.0f;

            #pragma unroll
            for (int ks = 0; ks < 4; ks++) {
                #pragma unroll
                for (int jp = 0; jp < 4; jp++) {
                    uint32_t b0, b1, b2, b3;
                    LDMX4(b0, b1, b2, b3,
                          kbase + (uint32_t)((((jp * 16 + krow) * KSTH) +
                                              ks * 16 + kcol) * 2));
                    uint32_t bf0[2] = { b0, b1 }, bf1[2] = { b2, b3 };
                    mma_f16(s[0][2 * jp],     qf[0][ks], bf0);
                    mma_f16(s[0][2 * jp + 1], qf[0][ks], bf1);
                    mma_f16(s[1][2 * jp],     qf[1][ks], bf0);
                    mma_f16(s[1][2 * jp + 1], qf[1][ks], bf1);
                }
            }

            #pragma unroll
            for (int rg = 0; rg < 2; rg++)
                #pragma unroll
                for (int j = 0; j < 8; j++)
                    #pragma unroll
                    for (int r = 0; r < 4; r++) s[rg][j][r] *= SC;

            #pragma unroll
            for (int rg = 0; rg < 2; rg++) {
                const int rb = q0 + wq0 + rg * 16;
                if (k0 + 63 > rb) {
                    const int rlo = rb + gr, rhi = rlo + 8;
                    #pragma unroll
                    for (int j = 0; j < 8; j++) {
                        const int col = k0 + j * 8 + gc * 2;
                        if (col     > rlo) s[rg][j][0] = -1e30f;
                        if (col + 1 > rlo) s[rg][j][1] = -1e30f;
                        if (col     > rhi) s[rg][j][2] = -1e30f;
                        if (col + 1 > rhi) s[rg][j][3] = -1e30f;
                    }
                }

                float mx_lo = -1e30f, mx_hi = -1e30f;
                #pragma unroll
                for (int j = 0; j < 8; j++) {
                    mx_lo = fmaxf(mx_lo, fmaxf(s[rg][j][0], s[rg][j][1]));
                    mx_hi = fmaxf(mx_hi, fmaxf(s[rg][j][2], s[rg][j][3]));
                }
                mx_lo = fmaxf(mx_lo, __shfl_xor_sync(0xffffffffu, mx_lo, 1));
                mx_lo = fmaxf(mx_lo, __shfl_xor_sync(0xffffffffu, mx_lo, 2));
                mx_hi = fmaxf(mx_hi, __shfl_xor_sync(0xffffffffu, mx_hi, 1));
                mx_hi = fmaxf(mx_hi, __shfl_xor_sync(0xffffffffu, mx_hi, 2));

                const float nm_lo = fmaxf(m_lo[rg], mx_lo);
                const float nm_hi = fmaxf(m_hi[rg], mx_hi);
                const float al_lo = exp2f(m_lo[rg] - nm_lo);
                const float al_hi = exp2f(m_hi[rg] - nm_hi);
                m_lo[rg] = nm_lo; m_hi[rg] = nm_hi;

                float sm_lo = 0.0f, sm_hi = 0.0f;
                #pragma unroll
                for (int j = 0; j < 8; j++) {
                    s[rg][j][0] = exp2f(s[rg][j][0] - nm_lo);
                    s[rg][j][1] = exp2f(s[rg][j][1] - nm_lo);
                    s[rg][j][2] = exp2f(s[rg][j][2] - nm_hi);
                    s[rg][j][3] = exp2f(s[rg][j][3] - nm_hi);
                    sm_lo += s[rg][j][0] + s[rg][j][1];
                    sm_hi += s[rg][j][2] + s[rg][j][3];
                }
                sm_lo += __shfl_xor_sync(0xffffffffu, sm_lo, 1);
                sm_lo += __shfl_xor_sync(0xffffffffu, sm_lo, 2);
                sm_hi += __shfl_xor_sync(0xffffffffu, sm_hi, 1);
                sm_hi += __shfl_xor_sync(0xffffffffu, sm_hi, 2);
                l_lo[rg] = l_lo[rg] * al_lo + sm_lo;
                l_hi[rg] = l_hi[rg] * al_hi + sm_hi;

                #pragma unroll
                for (int j = 0; j < 8; j++) {
                    o[rg][j][0] *= al_lo; o[rg][j][1] *= al_lo;
                    o[rg][j][2] *= al_hi; o[rg][j][3] *= al_hi;
                }
            }

            #pragma unroll
            for (int kk = 0; kk < 4; kk++) {
                uint32_t pf0[4], pf1[4];
                pf0[0] = packh2(s[0][2 * kk][0],     s[0][2 * kk][1]);
                pf0[1] = packh2(s[0][2 * kk][2],     s[0][2 * kk][3]);
                pf0[2] = packh2(s[0][2 * kk + 1][0], s[0][2 * kk + 1][1]);
                pf0[3] = packh2(s[0][2 * kk + 1][2], s[0][2 * kk + 1][3]);
                pf1[0] = packh2(s[1][2 * kk][0],     s[1][2 * kk][1]);
                pf1[1] = packh2(s[1][2 * kk][2],     s[1][2 * kk][3]);
                pf1[2] = packh2(s[1][2 * kk + 1][0], s[1][2 * kk + 1][1]);
                pf1[3] = packh2(s[1][2 * kk + 1][2], s[1][2 * kk + 1][3]);
                #pragma unroll
                for (int nb = 0; nb < 4; nb++) {
                    uint32_t b0, b1, b2, b3;
                    LDMX4T(b0, b1, b2, b3,
                           vbase + (uint32_t)((((kk * 16 + vrow) * VSTH) +
                                               nb * 16 + vcol) * 2));
                    uint32_t bf0[2] = { b0, b1 }, bf1[2] = { b2, b3 };
                    mma_f16(o[0][2 * nb],     pf0, bf0);
                    mma_f16(o[0][2 * nb + 1], pf0, bf1);
                    mma_f16(o[1][2 * nb],     pf1, bf0);
                    mma_f16(o[1][2 * nb + 1], pf1, bf1);
                }
            }
        }
        __syncthreads();
        buf ^= 1;
    }

    // ---- normalize + write half ----
    #pragma unroll
    for (int rg = 0; rg < 2; rg++) {
        const float il_lo = 1.0f / l_lo[rg];
        const float il_hi = 1.0f / l_hi[rg];
        __half* olo = outp + (size_t)(b * Tn + q0 + wq0 + rg * 16 + gr) * Cc
                           + h * HD + gc * 2;
        __half* ohi = olo + (size_t)8 * Cc;
        #pragma unroll
        for (int j2 = 0; j2 < 8; j2++) {
            *(__half2*)(olo + j2 * 8) =
                __floats2half2_rn(o[rg][j2][0] * il_lo, o[rg][j2][1] * il_lo);
            *(__half2*)(ohi + j2 * 8) =
                __floats2half2_rn(o[rg][j2][2] * il_hi, o[rg][j2][3] * il_hi);
        }
    }
}

// ===========================================================================
// Launch
// ===========================================================================
extern "C" void kernel_launch(void* const* d_in, const int* in_sizes, int n_in,
                              void* d_out, int out_size)
{
    const float* x      = (const float*)d_in[0];   // (B,T,C)
    const float* w_attn = (const float*)d_in[1];   // (3C, C)
    const float* w_proj = (const float*)d_in[2];   // (C, C)
    float* out = (float*)d_out;                    // (B,T,C)

    __half *xh_p, *wah_p, *wph_p, *qkv_p, *ath_p;
    cudaGetSymbolAddress((void**)&xh_p,  g_xh);
    cudaGetSymbolAddress((void**)&wah_p, g_wah);
    cudaGetSymbolAddress((void**)&wph_p, g_wph);
    cudaGetSymbolAddress((void**)&qkv_p, g_qkv);
    cudaGetSymbolAddress((void**)&ath_p, g_ath);

    cudaFuncSetAttribute(gemm_f16_kernel<0>,
                         cudaFuncAttributeMaxDynamicSharedMemorySize, GEMM_SMEM);
    cudaFuncSetAttribute(gemm_f16_kernel<1>,
                         cudaFuncAttributeMaxDynamicSharedMemorySize, GEMM_SMEM);
    cudaFuncSetAttribute(flash_tc_kernel,
                         cudaFuncAttributeMaxDynamicSharedMemorySize, FLASH_SMEM);

    // 0) convert inputs to half
    to_half_kernel<<<MTOT * Cc / 8 / 256, 256>>>((const float4*)x, (uint4*)xh_p,
                                                 MTOT * Cc / 8);
    to_half_kernel<<<3 * Cc * Cc / 8 / 256, 256>>>((const float4*)w_attn,
                                                   (uint4*)wah_p, 3 * Cc * Cc / 8);
    to_half_kernel<<<Cc * Cc / 8 / 256, 256>>>((const float4*)w_proj,
                                               (uint4*)wph_p, Cc * Cc / 8);

    // 1) QKV = x @ w_attn^T : M=8192, N=3072, K=1024 -> half (persistent grid)
    gemm_f16_kernel<1><<<GEMM_GRID, 256, GEMM_SMEM>>>(
        xh_p, wah_p, nullptr, qkv_p, MTOT, 3 * Cc, Cc);

    // 2) Flash attention -> att half
    {
        dim3 grid(Tn / QROWS, Bn * NH);
        flash_tc_kernel<<<grid, 128, FLASH_SMEM>>>(qkv_p, ath_p);
    }

    // 3) out = att @ w_proj^T : M=8192, N=1024, K=1024 (f32 out, persistent)
    gemm_f16_kernel<0><<<GEMM_GRID, 256, GEMM_SMEM>>>(
        ath_p, wph_p, out, nullptr, MTOT, Cc, Cc);
}

// round 14
// speedup vs baseline: 2.2006x; 1.0017x over previous
#include <cuda_runtime.h>
#include <cuda_fp16.h>
#include <math.h>
#include <stdint.h>

// Problem constants (B=4, T=2048, C=1024, H=16, D=64)
#define Bn   4
#define Tn   2048
#define Cc   1024
#define NH   16
#define HD   64
#define MTOT (Bn * Tn)          // 8192 rows

// Scratch (device globals: allocation is forbidden)
__device__ __half g_xh [(size_t)MTOT * Cc];        // x (half)
__device__ __half g_wah[(size_t)3 * Cc * Cc];      // w_attn (half)
__device__ __half g_wph[(size_t)Cc * Cc];          // w_proj (half)
__device__ __half g_qkv[(size_t)MTOT * 3 * Cc];    // qkv (half), (B*T, 3C)
__device__ __half g_ath[(size_t)MTOT * Cc];        // attention out (half)

// ===========================================================================
// Helpers
// ===========================================================================
__device__ __forceinline__ uint32_t smem_u32(const void* p) {
    uint32_t a;
    asm("{ .reg .u64 t; cvta.to.shared.u64 t, %1; cvt.u32.u64 %0, t; }"
        : "=r"(a) : "l"(p));
    return a;
}
__device__ __forceinline__ uint32_t packh2(float a, float b) {
    __half2 h = __floats2half2_rn(a, b);
    return *(uint32_t*)&h;
}
// fp16 mma: D(16x8,f32) = A(16x16,f16,row) @ B(16x8,f16,col) + D
__device__ __forceinline__ void mma_f16(float* c, const uint32_t* a, const uint32_t* b) {
    asm volatile(
        "mma.sync.aligned.m16n8k16.row.col.f32.f16.f16.f32 "
        "{%0,%1,%2,%3}, {%4,%5,%6,%7}, {%8,%9}, {%0,%1,%2,%3};"
        : "+f"(c[0]), "+f"(c[1]), "+f"(c[2]), "+f"(c[3])
        : "r"(a[0]), "r"(a[1]), "r"(a[2]), "r"(a[3]), "r"(b[0]), "r"(b[1]));
}
#define LDMX4(r0,r1,r2,r3,addr) \
    asm volatile("ldmatrix.sync.aligned.m8n8.x4.shared.b16 {%0,%1,%2,%3}, [%4];" \
        : "=r"(r0), "=r"(r1), "=r"(r2), "=r"(r3) : "r"(addr))
#define LDMX4T(r0,r1,r2,r3,addr) \
    asm volatile("ldmatrix.sync.aligned.m8n8.x4.trans.shared.b16 {%0,%1,%2,%3}, [%4];" \
        : "=r"(r0), "=r"(r1), "=r"(r2), "=r"(r3) : "r"(addr))
#define CP16(smem, gmem) \
    asm volatile("cp.async.cg.shared.global [%0], [%1], 16;" \
                 :: "r"(smem), "l"(gmem) : "memory")
#define CP_COMMIT() asm volatile("cp.async.commit_group;" ::: "memory")
#define CP_WAIT0()  asm volatile("cp.async.wait_group 0;" ::: "memory")
#define CP_WAIT1()  asm volatile("cp.async.wait_group 1;" ::: "memory")

// ===========================================================================
// Convert pass: fp32 -> fp16 (8 elems / thread, 16B stores)
// ===========================================================================
__global__ __launch_bounds__(256) void to_half_kernel(
    const float4* __restrict__ in, uint4* __restrict__ out, int n8)
{
    int i = blockIdx.x * blockDim.x + threadIdx.x;
    if (i < n8) {
        float4 a = in[2 * i], b = in[2 * i + 1];
        uint4 o = { packh2(a.x, a.y), packh2(a.z, a.w),
                    packh2(b.x, b.y), packh2(b.z, b.w) };
        out[i] = o;
    }
}

// ===========================================================================
// FP16 GEMM (PERSISTENT, 64x64 warp tiles): C[M,N] = A[M,K] @ B[N,K]^T.
// CTA tile 128x128, 128 thr (4 warps, 2x2 grid, 64x64/warp), BK=64, 2-stage.
// 8 LDSM per 32 mma (1:4) -> ldmatrix floor no longer binds the tensor pipe.
// Smem stride 72 halves (144B = 9x16B): ldmatrix conflict-free.
// MODE 0: C f32 out.  MODE 1: half out (qkv).
// ===========================================================================
#define GH_ST  72
#define HTILE  (128 * GH_ST)                  // 9216 halves per (A or B) tile
#define HSTAGE (2 * HTILE)                    // 36864 B
#define GEMM_SMEM (2 * HSTAGE * 2)            // 73728 B
#define GEMM_GRID 304                         // 2 CTAs/SM x 152 SMs

template <int MODE>
__global__ __launch_bounds__(128, 2) void gemm_f16_kernel(
    const __half* __restrict__ A, const __half* __restrict__ B,
    float* __restrict__ C, __half* __restrict__ HC, int M, int N, int K)
{
    extern __shared__ char smc[];
    const uint32_t sb = smem_u32(smc);
    const int tid = threadIdx.x;
    const int wid = tid >> 5, lane = tid & 31;
    const int gr = lane >> 2, gc = lane & 3;
    const int wm0 = (wid >> 1) * 64, wn0 = (wid & 1) * 64;

    // ldmatrix lane geometry
    const uint32_t arow = (lane & 7) + ((lane >> 3) & 1) * 8;
    const uint32_t acol = (lane >> 4) * 8;
    const uint32_t brow = (lane & 7) + (lane >> 4) * 8;
    const uint32_t bcol = ((lane >> 3) & 1) * 8;

    // loader: 16 rows x 64 halves per pass, 8 passes per 128-row tile
    const int rl = tid >> 3;            // 0..15
    const int cl = (tid & 7) * 8;       // halves

    const int KCH = K / 64;
    const int NX = N / 128;
    const int ntiles = (M / 128) * NX;

    for (int t = blockIdx.x; t < ntiles; t += gridDim.x) {
        const int m0 = (t / NX) * 128, n0 = (t % NX) * 128;

        float acc[4][8][4];
        #pragma unroll
        for (int i = 0; i < 4; i++)
            #pragma unroll
            for (int j = 0; j < 8; j++)
                #pragma unroll
                for (int r = 0; r < 4; r++) acc[i][j][r] = 0.0f;

        const __half* Ag = A + (size_t)(m0 + rl) * K + cl;
        const __half* Bg = B + (size_t)(n0 + rl) * K + cl;

        // prefetch chunks 0,1
        #pragma unroll
        for (int s = 0; s < 2; s++) {
            const uint32_t st = sb + (uint32_t)(s * HSTAGE * 2);
            #pragma unroll
            for (int it = 0; it < 8; it++) {
                uint32_t off = (uint32_t)(((rl + it * 16) * GH_ST + cl) * 2);
                CP16(st + off,             Ag + (size_t)it * 16 * K + s * 64);
                CP16(st + off + HTILE * 2, Bg + (size_t)it * 16 * K + s * 64);
            }
            CP_COMMIT();
        }

        for (int c = 0; c < KCH; c++) {
            if (c + 1 < KCH) { CP_WAIT1(); } else { CP_WAIT0(); }
            __syncthreads();

            const uint32_t sA = sb + (uint32_t)((c & 1) * HSTAGE * 2);
            const uint32_t sB = sA + (uint32_t)(HTILE * 2);
            #pragma unroll
            for (int ks = 0; ks < 4; ks++) {
                uint32_t af[4][4], bf[8][2];
                #pragma unroll
                for (int i = 0; i < 4; i++)
                    LDMX4(af[i][0], af[i][1], af[i][2], af[i][3],
                          sA + (uint32_t)((((wm0 + i * 16 + arow) * GH_ST) +
                                           ks * 16 + acol) * 2));
                #pragma unroll
                for (int jp = 0; jp < 4; jp++) {
                    uint32_t b0, b1, b2, b3;
                    LDMX4(b0, b1, b2, b3,
                          sB + (uint32_t)((((wn0 + jp * 16 + brow) * GH_ST) +
                                           ks * 16 + bcol) * 2));
                    bf[2 * jp][0] = b0; bf[2 * jp][1] = b1;
                    bf[2 * jp + 1][0] = b2; bf[2 * jp + 1][1] = b3;
                }
                #pragma unroll
                for (int i = 0; i < 4; i++)
                    #pragma unroll
                    for (int j = 0; j < 8; j++)
                        mma_f16(acc[i][j], af[i], bf[j]);
            }
            __syncthreads();

            if (c + 2 < KCH) {
                const uint32_t st = sb + (uint32_t)((c & 1) * HSTAGE * 2);
                #pragma unroll
                for (int it = 0; it < 8; it++) {
                    uint32_t off = (uint32_t)(((rl + it * 16) * GH_ST + cl) * 2);
                    CP16(st + off,             Ag + (size_t)it * 16 * K + (c + 2) * 64);
                    CP16(st + off + HTILE * 2, Bg + (size_t)it * 16 * K + (c + 2) * 64);
                }
                CP_COMMIT();
            }
        }

        // epilogue
        #pragma unroll
        for (int i = 0; i < 4; i++)
            #pragma unroll
            for (int j = 0; j < 8; j++) {
                const int row = m0 + wm0 + i * 16 + gr;
                const int col = n0 + wn0 + j * 8 + gc * 2;
                if (MODE == 0) {
                    float* cr = C + (size_t)row * N + col;
                    float2 v0 = { acc[i][j][0], acc[i][j][1] };
                    float2 v1 = { acc[i][j][2], acc[i][j][3] };
                    *(float2*)cr           = v0;
                    *(float2*)(cr + 8 * N) = v1;
                } else {
                    __half* hr = HC + (size_t)row * N + col;
                    *(__half2*)hr                   = __floats2half2_rn(acc[i][j][0], acc[i][j][1]);
                    *(__half2*)(hr + (size_t)8 * N) = __floats2half2_rn(acc[i][j][2], acc[i][j][3]);
                }
            }
    }
}

// ===========================================================================
// Flash attention (causal), all-fp16 mma, f32 accum/softmax. (unchanged R12)
// ===========================================================================
#define KSTH 72
#define VSTH 72
#define QROWS 128
#define FLASH_SMEM ((2 * 64 * KSTH + 2 * 64 * VSTH) * 2)   // 36864 B

__global__ __launch_bounds__(128, 2) void flash_tc_kernel(
    const __half* __restrict__ qkv, __half* __restrict__ outp)
{
    extern __shared__ char smc[];
    __half* Ksm = (__half*)smc;                   // [2][64*KSTH]
    __half* Vsm = Ksm + 2 * 64 * KSTH;            // [2][64*VSTH]
    const uint32_t sbK = smem_u32(Ksm);
    const uint32_t sbV = smem_u32(Vsm);

    const int tid = threadIdx.x;
    const int wid = tid >> 5, lane = tid & 31;
    const int gr = lane >> 2, gc = lane & 3;
    const int qt = gridDim.x - 1 - blockIdx.x;    // heavy tiles first
    const int b  = blockIdx.y >> 4;
    const int h  = blockIdx.y & 15;
    const int q0 = qt * QROWS;
    const int wq0 = wid * 32;
    const size_t rst = 3 * Cc;

    const uint32_t krow = (lane & 7) + (lane >> 4) * 8;
    const uint32_t kcol = ((lane >> 3) & 1) * 8;
    const uint32_t vrow = lane & 15;
    const uint32_t vcol = (lane >> 4) * 8;

    // ---- Q fragments ----
    uint32_t qf[2][4][4];
    #pragma unroll
    for (int rg = 0; rg < 2; rg++) {
        const __half* qlo = qkv + (size_t)(b * Tn + q0 + wq0 + rg * 16 + gr) * rst
                                + h * HD;
        const __half* qhi = qlo + 8 * rst;
        #pragma unroll
        for (int ks = 0; ks < 4; ks++) {
            qf[rg][ks][0] = *(const uint32_t*)(qlo + ks * 16 + gc * 2);
            qf[rg][ks][1] = *(const uint32_t*)(qhi + ks * 16 + gc * 2);
            qf[rg][ks][2] = *(const uint32_t*)(qlo + ks * 16 + gc * 2 + 8);
            qf[rg][ks][3] = *(const uint32_t*)(qhi + ks * 16 + gc * 2 + 8);
        }
    }

    float o[2][8][4];
    #pragma unroll
    for (int rg = 0; rg < 2; rg++)
        #pragma unroll
        for (int j = 0; j < 8; j++)
            #pragma unroll
            for (int r = 0; r < 4; r++) o[rg][j][r] = 0.0f;
    float m_lo[2] = {-1e30f, -1e30f}, m_hi[2] = {-1e30f, -1e30f};
    float l_lo[2] = {0.0f, 0.0f},     l_hi[2] = {0.0f, 0.0f};

    const int rl = tid >> 3;
    const int cl = (tid & 7) * 8;
    const __half* kb0 = qkv + (size_t)(b * Tn) * rst + Cc + h * HD;
    const __half* vb0 = qkv + (size_t)(b * Tn) * rst + 2 * Cc + h * HD;

    #pragma unroll
    for (int it = 0; it < 4; it++) {
        const int row = rl + it * 16;
        CP16(sbK + (uint32_t)((row * KSTH + cl) * 2), kb0 + (size_t)row * rst + cl);
        CP16(sbV + (uint32_t)((row * VSTH + cl) * 2), vb0 + (size_t)row * rst + cl);
    }
    CP_COMMIT();

    const float SC = 0.125f * 1.4426950408889634f;   // scale * log2(e)
    const int last = 2 * qt + 1;
    int buf = 0;
    for (int kt = 0; kt <= last; kt++) {
        if (kt < last) {
            const int nb = buf ^ 1;
            const __half* kb = kb0 + (size_t)(kt + 1) * 64 * rst;
            const __half* vb = vb0 + (size_t)(kt + 1) * 64 * rst;
            #pragma unroll
            for (int it = 0; it < 4; it++) {
                const int row = rl + it * 16;
                CP16(sbK + (uint32_t)(((nb * 64 + row) * KSTH + cl) * 2),
                     kb + (size_t)row * rst + cl);
                CP16(sbV + (uint32_t)(((nb * 64 + row) * VSTH + cl) * 2),
                     vb + (size_t)row * rst + cl);
            }
            CP_COMMIT();
            CP_WAIT1();
        } else {
            CP_WAIT0();
        }
        __syncthreads();

        const int k0 = kt * 64;
        if (k0 <= q0 + wq0 + 31) {
            const uint32_t kbase = sbK + (uint32_t)(buf * 64 * KSTH * 2);
            const uint32_t vbase = sbV + (uint32_t)(buf * 64 * VSTH * 2);

            float s[2][8][4];
            #pragma unroll
            for (int rg = 0; rg < 2; rg++)
                #pragma unroll
                for (int j = 0; j < 8; j++)
                    #pragma unroll
                    for (int r = 0; r < 4; r++) s[rg][j][r] = 0.0f;

            #pragma unroll
            for (int ks = 0; ks < 4; ks++) {
                #pragma unroll
                for (int jp = 0; jp < 4; jp++) {
                    uint32_t b0, b1, b2, b3;
                    LDMX4(b0, b1, b2, b3,
                          kbase + (uint32_t)((((jp * 16 + krow) * KSTH) +
                                              ks * 16 + kcol) * 2));
                    uint32_t bf0[2] = { b0, b1 }, bf1[2] = { b2, b3 };
                    mma_f16(s[0][2 * jp],     qf[0][ks], bf0);
                    mma_f16(s[0][2 * jp + 1], qf[0][ks], bf1);
                    mma_f16(s[1][2 * jp],     qf[1][ks], bf0);
                    mma_f16(s[1][2 * jp + 1], qf[1][ks], bf1);
                }
            }

            #pragma unroll
            for (int rg = 0; rg < 2; rg++)
                #pragma unroll
                for (int j = 0; j < 8; j++)
                    #pragma unroll
                    for (int r = 0; r < 4; r++) s[rg][j][r] *= SC;

            #pragma unroll
            for (int rg = 0; rg < 2; rg++) {
                const int rb = q0 + wq0 + rg * 16;
                if (k0 + 63 > rb) {
                    const int rlo = rb + gr, rhi = rlo + 8;
                    #pragma unroll
                    for (int j = 0; j < 8; j++) {
                        const int col = k0 + j * 8 + gc * 2;
                        if (col     > rlo) s[rg][j][0] = -1e30f;
                        if (col + 1 > rlo) s[rg][j][1] = -1e30f;
                        if (col     > rhi) s[rg][j][2] = -1e30f;
                        if (col + 1 > rhi) s[rg][j][3] = -1e30f;
                    }
                }

                float mx_lo = -1e30f, mx_hi = -1e30f;
                #pragma unroll
                for (int j = 0; j < 8; j++) {
                    mx_lo = fmaxf(mx_lo, fmaxf(s[rg][j][0], s[rg][j][1]));
                    mx_hi = fmaxf(mx_hi, fmaxf(s[rg][j][2], s[rg][j][3]));
                }
                mx_lo = fmaxf(mx_lo, __shfl_xor_sync(0xffffffffu, mx_lo, 1));
                mx_lo = fmaxf(mx_lo, __shfl_xor_sync(0xffffffffu, mx_lo, 2));
                mx_hi = fmaxf(mx_hi, __shfl_xor_sync(0xffffffffu, mx_hi, 1));
                mx_hi = fmaxf(mx_hi, __shfl_xor_sync(0xffffffffu, mx_hi, 2));

                const float nm_lo = fmaxf(m_lo[rg], mx_lo);
                const float nm_hi = fmaxf(m_hi[rg], mx_hi);
                const float al_lo = exp2f(m_lo[rg] - nm_lo);
                const float al_hi = exp2f(m_hi[rg] - nm_hi);
                m_lo[rg] = nm_lo; m_hi[rg] = nm_hi;

                float sm_lo = 0.0f, sm_hi = 0.0f;
                #pragma unroll
                for (int j = 0; j < 8; j++) {
                    s[rg][j][0] = exp2f(s[rg][j][0] - nm_lo);
                    s[rg][j][1] = exp2f(s[rg][j][1] - nm_lo);
                    s[rg][j][2] = exp2f(s[rg][j][2] - nm_hi);
                    s[rg][j][3] = exp2f(s[rg][j][3] - nm_hi);
                    sm_lo += s[rg][j][0] + s[rg][j][1];
                    sm_hi += s[rg][j][2] + s[rg][j][3];
                }
                sm_lo += __shfl_xor_sync(0xffffffffu, sm_lo, 1);
                sm_lo += __shfl_xor_sync(0xffffffffu, sm_lo, 2);
                sm_hi += __shfl_xor_sync(0xffffffffu, sm_hi, 1);
                sm_hi += __shfl_xor_sync(0xffffffffu, sm_hi, 2);
                l_lo[rg] = l_lo[rg] * al_lo + sm_lo;
                l_hi[rg] = l_hi[rg] * al_hi + sm_hi;

                #pragma unroll
                for (int j = 0; j < 8; j++) {
                    o[rg][j][0] *= al_lo; o[rg][j][1] *= al_lo;
                    o[rg][j][2] *= al_hi; o[rg][j][3] *= al_hi;
                }
            }

            #pragma unroll
            for (int kk = 0; kk < 4; kk++) {
                uint32_t pf0[4], pf1[4];
                pf0[0] = packh2(s[0][2 * kk][0],     s[0][2 * kk][1]);
                pf0[1] = packh2(s[0][2 * kk][2],     s[0][2 * kk][3]);
                pf0[2] = packh2(s[0][2 * kk + 1][0], s[0][2 * kk + 1][1]);
                pf0[3] = packh2(s[0][2 * kk + 1][2], s[0][2 * kk + 1][3]);
                pf1[0] = packh2(s[1][2 * kk][0],     s[1][2 * kk][1]);
                pf1[1] = packh2(s[1][2 * kk][2],     s[1][2 * kk][3]);
                pf1[2] = packh2(s[1][2 * kk + 1][0], s[1][2 * kk + 1][1]);
                pf1[3] = packh2(s[1][2 * kk + 1][2], s[1][2 * kk + 1][3]);
                #pragma unroll
                for (int nb = 0; nb < 4; nb++) {
                    uint32_t b0, b1, b2, b3;
                    LDMX4T(b0, b1, b2, b3,
                           vbase + (uint32_t)((((kk * 16 + vrow) * VSTH) +
                                               nb * 16 + vcol) * 2));
                    uint32_t bf0[2] = { b0, b1 }, bf1[2] = { b2, b3 };
                    mma_f16(o[0][2 * nb],     pf0, bf0);
                    mma_f16(o[0][2 * nb + 1], pf0, bf1);
                    mma_f16(o[1][2 * nb],     pf1, bf0);
                    mma_f16(o[1][2 * nb + 1], pf1, bf1);
                }
            }
        }
        __syncthreads();
        buf ^= 1;
    }

    // ---- normalize + write half ----
    #pragma unroll
    for (int rg = 0; rg < 2; rg++) {
        const float il_lo = 1.0f / l_lo[rg];
        const float il_hi = 1.0f / l_hi[rg];
        __half* olo = outp + (size_t)(b * Tn + q0 + wq0 + rg * 16 + gr) * Cc
                           + h * HD + gc * 2;
        __half* ohi = olo + (size_t)8 * Cc;
        #pragma unroll
        for (int j2 = 0; j2 < 8; j2++) {
            *(__half2*)(olo + j2 * 8) =
                __floats2half2_rn(o[rg][j2][0] * il_lo, o[rg][j2][1] * il_lo);
            *(__half2*)(ohi + j2 * 8) =
                __floats2half2_rn(o[rg][j2][2] * il_hi, o[rg][j2][3] * il_hi);
        }
    }
}

// ===========================================================================
// Launch
// ===========================================================================
extern "C" void kernel_launch(void* const* d_in, const int* in_sizes, int n_in,
                              void* d_out, int out_size)
{
    const float* x      = (const float*)d_in[0];   // (B,T,C)
    const float* w_attn = (const float*)d_in[1];   // (3C, C)
    const float* w_proj = (const float*)d_in[2];   // (C, C)
    float* out = (float*)d_out;                    // (B,T,C)

    __half *xh_p, *wah_p, *wph_p, *qkv_p, *ath_p;
    cudaGetSymbolAddress((void**)&xh_p,  g_xh);
    cudaGetSymbolAddress((void**)&wah_p, g_wah);
    cudaGetSymbolAddress((void**)&wph_p, g_wph);
    cudaGetSymbolAddress((void**)&qkv_p, g_qkv);
    cudaGetSymbolAddress((void**)&ath_p, g_ath);

    cudaFuncSetAttribute(gemm_f16_kernel<0>,
                         cudaFuncAttributeMaxDynamicSharedMemorySize, GEMM_SMEM);
    cudaFuncSetAttribute(gemm_f16_kernel<1>,
                         cudaFuncAttributeMaxDynamicSharedMemorySize, GEMM_SMEM);
    cudaFuncSetAttribute(flash_tc_kernel,
                         cudaFuncAttributeMaxDynamicSharedMemorySize, FLASH_SMEM);

    // 0) convert inputs to half
    to_half_kernel<<<MTOT * Cc / 8 / 256, 256>>>((const float4*)x, (uint4*)xh_p,
                                                 MTOT * Cc / 8);
    to_half_kernel<<<3 * Cc * Cc / 8 / 256, 256>>>((const float4*)w_attn,
                                                   (uint4*)wah_p, 3 * Cc * Cc / 8);
    to_half_kernel<<<Cc * Cc / 8 / 256, 256>>>((const float4*)w_proj,
                                               (uint4*)wph_p, Cc * Cc / 8);

    // 1) QKV = x @ w_attn^T : M=8192, N=3072, K=1024 -> half (persistent)
    gemm_f16_kernel<1><<<GEMM_GRID, 128, GEMM_SMEM>>>(
        xh_p, wah_p, nullptr, qkv_p, MTOT, 3 * Cc, Cc);

    // 2) Flash attention -> att half
    {
        dim3 grid(Tn / QROWS, Bn * NH);
        flash_tc_kernel<<<grid, 128, FLASH_SMEM>>>(qkv_p, ath_p);
    }

    // 3) out = att @ w_proj^T : M=8192, N=1024, K=1024 (f32 out, persistent)
    gemm_f16_kernel<0><<<GEMM_GRID, 128, GEMM_SMEM>>>(
        ath_p, wph_p, out, nullptr, MTOT, Cc, Cc);
}

// round 15
// speedup vs baseline: 2.3384x; 1.0626x over previous
#include <cuda_runtime.h>
#include <cuda_fp16.h>
#include <math.h>
#include <stdint.h>

// Problem constants (B=4, T=2048, C=1024, H=16, D=64)
#define Bn   4
#define Tn   2048
#define Cc   1024
#define NH   16
#define HD   64
#define MTOT (Bn * Tn)          // 8192 rows

// Scratch (device globals: allocation is forbidden)
__device__ __half g_xh [(size_t)MTOT * Cc];        // x (half)
__device__ __half g_wah[(size_t)3 * Cc * Cc];      // w_attn (half)
__device__ __half g_wph[(size_t)Cc * Cc];          // w_proj (half)
__device__ __half g_qkv[(size_t)MTOT * 3 * Cc];    // qkv (half), (B*T, 3C)
__device__ __half g_ath[(size_t)MTOT * Cc];        // attention out (half)

// ===========================================================================
// Helpers
// ===========================================================================
__device__ __forceinline__ uint32_t smem_u32(const void* p) {
    uint32_t a;
    asm("{ .reg .u64 t; cvta.to.shared.u64 t, %1; cvt.u32.u64 %0, t; }"
        : "=r"(a) : "l"(p));
    return a;
}
__device__ __forceinline__ uint32_t packh2(float a, float b) {
    __half2 h = __floats2half2_rn(a, b);
    return *(uint32_t*)&h;
}
// fp16 mma: D(16x8,f32) = A(16x16,f16,row) @ B(16x8,f16,col) + D
__device__ __forceinline__ void mma_f16(float* c, const uint32_t* a, const uint32_t* b) {
    asm volatile(
        "mma.sync.aligned.m16n8k16.row.col.f32.f16.f16.f32 "
        "{%0,%1,%2,%3}, {%4,%5,%6,%7}, {%8,%9}, {%0,%1,%2,%3};"
        : "+f"(c[0]), "+f"(c[1]), "+f"(c[2]), "+f"(c[3])
        : "r"(a[0]), "r"(a[1]), "r"(a[2]), "r"(a[3]), "r"(b[0]), "r"(b[1]));
}
#define LDMX4(r0,r1,r2,r3,addr) \
    asm volatile("ldmatrix.sync.aligned.m8n8.x4.shared.b16 {%0,%1,%2,%3}, [%4];" \
        : "=r"(r0), "=r"(r1), "=r"(r2), "=r"(r3) : "r"(addr))
#define LDMX4T(r0,r1,r2,r3,addr) \
    asm volatile("ldmatrix.sync.aligned.m8n8.x4.trans.shared.b16 {%0,%1,%2,%3}, [%4];" \
        : "=r"(r0), "=r"(r1), "=r"(r2), "=r"(r3) : "r"(addr))
#define CP16(smem, gmem) \
    asm volatile("cp.async.cg.shared.global [%0], [%1], 16;" \
                 :: "r"(smem), "l"(gmem) : "memory")
#define CP_COMMIT() asm volatile("cp.async.commit_group;" ::: "memory")
#define CP_WAIT0()  asm volatile("cp.async.wait_group 0;" ::: "memory")
#define CP_WAIT1()  asm volatile("cp.async.wait_group 1;" ::: "memory")

// ===========================================================================
// Fused convert pass: x, w_attn, w_proj fp32 -> fp16 in ONE launch
// ===========================================================================
__global__ __launch_bounds__(256) void to_half3_kernel(
    const float4* __restrict__ x,  uint4* __restrict__ xh,  int n8x,
    const float4* __restrict__ wa, uint4* __restrict__ wah, int n8a,
    const float4* __restrict__ wp, uint4* __restrict__ wph, int n8p)
{
    int i = blockIdx.x * blockDim.x + threadIdx.x;
    const float4* in;
    uint4* out;
    int idx;
    if (i < n8x)            { in = x;  out = xh;  idx = i; }
    else if (i < n8x + n8a) { in = wa; out = wah; idx = i - n8x; }
    else if (i < n8x + n8a + n8p) { in = wp; out = wph; idx = i - n8x - n8a; }
    else return;
    float4 a = in[2 * idx], b = in[2 * idx + 1];
    uint4 o = { packh2(a.x, a.y), packh2(a.z, a.w),
                packh2(b.x, b.y), packh2(b.z, b.w) };
    out[idx] = o;
}

// ===========================================================================
// FP16 GEMM (PERSISTENT, 3-stage, loads-first): C[M,N] = A[M,K] @ B[N,K]^T.
// CTA tile 128x128, 128 thr (4 warps 2x2, 64x64/warp), BK=64.
// Per chunk: wait(<=1) -> ONE sync -> issue c+2 -> compute c.
// 3rd buffer makes issue-before-compute safe (target buf last read at c-1,
// which all warps finished before this sync). Full-chunk latency hiding.
// Smem stride 72 halves (144B = 9x16B): ldmatrix conflict-free.
// MODE 0: C f32 out.  MODE 1: half out (qkv).
// ===========================================================================
#define GH_ST  72
#define HTILE  (128 * GH_ST)                  // 9216 halves per (A or B) tile
#define HSTAGE (2 * HTILE)                    // 36864 B
#define GEMM_SMEM (3 * HSTAGE * 2)            // 110592 B (x2 CTAs = 221KB <= 228KB)
#define GEMM_GRID 304                         // 2 CTAs/SM x 152 SMs

template <int MODE>
__global__ __launch_bounds__(128, 2) void gemm_f16_kernel(
    const __half* __restrict__ A, const __half* __restrict__ B,
    float* __restrict__ C, __half* __restrict__ HC, int M, int N, int K)
{
    extern __shared__ char smc[];
    const uint32_t sb = smem_u32(smc);
    const int tid = threadIdx.x;
    const int wid = tid >> 5, lane = tid & 31;
    const int gr = lane >> 2, gc = lane & 3;
    const int wm0 = (wid >> 1) * 64, wn0 = (wid & 1) * 64;

    // ldmatrix lane geometry
    const uint32_t arow = (lane & 7) + ((lane >> 3) & 1) * 8;
    const uint32_t acol = (lane >> 4) * 8;
    const uint32_t brow = (lane & 7) + (lane >> 4) * 8;
    const uint32_t bcol = ((lane >> 3) & 1) * 8;

    // loader: 16 rows x 64 halves per pass, 8 passes per 128-row tile
    const int rl = tid >> 3;            // 0..15
    const int cl = (tid & 7) * 8;       // halves

    const int KCH = K / 64;
    const int NX = N / 128;
    const int ntiles = (M / 128) * NX;

    for (int t = blockIdx.x; t < ntiles; t += gridDim.x) {
        const int m0 = (t / NX) * 128, n0 = (t % NX) * 128;

        float acc[4][8][4];
        #pragma unroll
        for (int i = 0; i < 4; i++)
            #pragma unroll
            for (int j = 0; j < 8; j++)
                #pragma unroll
                for (int r = 0; r < 4; r++) acc[i][j][r] = 0.0f;

        const __half* Ag = A + (size_t)(m0 + rl) * K + cl;
        const __half* Bg = B + (size_t)(n0 + rl) * K + cl;

        // prefetch chunks 0,1 into stages 0,1
        #pragma unroll
        for (int s = 0; s < 2; s++) {
            const uint32_t st = sb + (uint32_t)(s * HSTAGE * 2);
            #pragma unroll
            for (int it = 0; it < 8; it++) {
                uint32_t off = (uint32_t)(((rl + it * 16) * GH_ST + cl) * 2);
                CP16(st + off,             Ag + (size_t)it * 16 * K + s * 64);
                CP16(st + off + HTILE * 2, Bg + (size_t)it * 16 * K + s * 64);
            }
            CP_COMMIT();
        }

        for (int c = 0; c < KCH; c++) {
            // wait for chunk c's group (keep c+1 in flight)
            if (c + 1 < KCH) { CP_WAIT1(); } else { CP_WAIT0(); }
            __syncthreads();

            // issue loads for chunk c+2 into stage (c+2)%3 BEFORE compute
            if (c + 2 < KCH) {
                const uint32_t st = sb + (uint32_t)(((c + 2) % 3) * HSTAGE * 2);
                #pragma unroll
                for (int it = 0; it < 8; it++) {
                    uint32_t off = (uint32_t)(((rl + it * 16) * GH_ST + cl) * 2);
                    CP16(st + off,             Ag + (size_t)it * 16 * K + (c + 2) * 64);
                    CP16(st + off + HTILE * 2, Bg + (size_t)it * 16 * K + (c + 2) * 64);
                }
                CP_COMMIT();
            }

            // compute chunk c
            const uint32_t sA = sb + (uint32_t)((c % 3) * HSTAGE * 2);
            const uint32_t sB = sA + (uint32_t)(HTILE * 2);
            #pragma unroll
            for (int ks = 0; ks < 4; ks++) {
                uint32_t af[4][4], bf[8][2];
                #pragma unroll
                for (int i = 0; i < 4; i++)
                    LDMX4(af[i][0], af[i][1], af[i][2], af[i][3],
                          sA + (uint32_t)((((wm0 + i * 16 + arow) * GH_ST) +
                                           ks * 16 + acol) * 2));
                #pragma unroll
                for (int jp = 0; jp < 4; jp++) {
                    uint32_t b0, b1, b2, b3;
                    LDMX4(b0, b1, b2, b3,
                          sB + (uint32_t)((((wn0 + jp * 16 + brow) * GH_ST) +
                                           ks * 16 + bcol) * 2));
                    bf[2 * jp][0] = b0; bf[2 * jp][1] = b1;
                    bf[2 * jp + 1][0] = b2; bf[2 * jp + 1][1] = b3;
                }
                #pragma unroll
                for (int i = 0; i < 4; i++)
                    #pragma unroll
                    for (int j = 0; j < 8; j++)
                        mma_f16(acc[i][j], af[i], bf[j]);
            }
        }
        __syncthreads();   // all warps done with last buffers before next tile

        // epilogue
        #pragma unroll
        for (int i = 0; i < 4; i++)
            #pragma unroll
            for (int j = 0; j < 8; j++) {
                const int row = m0 + wm0 + i * 16 + gr;
                const int col = n0 + wn0 + j * 8 + gc * 2;
                if (MODE == 0) {
                    float* cr = C + (size_t)row * N + col;
                    float2 v0 = { acc[i][j][0], acc[i][j][1] };
                    float2 v1 = { acc[i][j][2], acc[i][j][3] };
                    *(float2*)cr           = v0;
                    *(float2*)(cr + 8 * N) = v1;
                } else {
                    __half* hr = HC + (size_t)row * N + col;
                    *(__half2*)hr                   = __floats2half2_rn(acc[i][j][0], acc[i][j][1]);
                    *(__half2*)(hr + (size_t)8 * N) = __floats2half2_rn(acc[i][j][2], acc[i][j][3]);
                }
            }
    }
}

// ===========================================================================
// Flash attention (causal), all-fp16 mma, f32 accum/softmax. (unchanged)
// ===========================================================================
#define KSTH 72
#define VSTH 72
#define QROWS 128
#define FLASH_SMEM ((2 * 64 * KSTH + 2 * 64 * VSTH) * 2)   // 36864 B

__global__ __launch_bounds__(128, 2) void flash_tc_kernel(
    const __half* __restrict__ qkv, __half* __restrict__ outp)
{
    extern __shared__ char smc[];
    __half* Ksm = (__half*)smc;                   // [2][64*KSTH]
    __half* Vsm = Ksm + 2 * 64 * KSTH;            // [2][64*VSTH]
    const uint32_t sbK = smem_u32(Ksm);
    const uint32_t sbV = smem_u32(Vsm);

    const int tid = threadIdx.x;
    const int wid = tid >> 5, lane = tid & 31;
    const int gr = lane >> 2, gc = lane & 3;
    const int qt = gridDim.x - 1 - blockIdx.x;    // heavy tiles first
    const int b  = blockIdx.y >> 4;
    const int h  = blockIdx.y & 15;
    const int q0 = qt * QROWS;
    const int wq0 = wid * 32;
    const size_t rst = 3 * Cc;

    const uint32_t krow = (lane & 7) + (lane >> 4) * 8;
    const uint32_t kcol = ((lane >> 3) & 1) * 8;
    const uint32_t vrow = lane & 15;
    const uint32_t vcol = (lane >> 4) * 8;

    // ---- Q fragments ----
    uint32_t qf[2][4][4];
    #pragma unroll
    for (int rg = 0; rg < 2; rg++) {
        const __half* qlo = qkv + (size_t)(b * Tn + q0 + wq0 + rg * 16 + gr) * rst
                                + h * HD;
        const __half* qhi = qlo + 8 * rst;
        #pragma unroll
        for (int ks = 0; ks < 4; ks++) {
            qf[rg][ks][0] = *(const uint32_t*)(qlo + ks * 16 + gc * 2);
            qf[rg][ks][1] = *(const uint32_t*)(qhi + ks * 16 + gc * 2);
            qf[rg][ks][2] = *(const uint32_t*)(qlo + ks * 16 + gc * 2 + 8);
            qf[rg][ks][3] = *(const uint32_t*)(qhi + ks * 16 + gc * 2 + 8);
        }
    }

    float o[2][8][4];
    #pragma unroll
    for (int rg = 0; rg < 2; rg++)
        #pragma unroll
        for (int j = 0; j < 8; j++)
            #pragma unroll
            for (int r = 0; r < 4; r++) o[rg][j][r] = 0.0f;
    float m_lo[2] = {-1e30f, -1e30f}, m_hi[2] = {-1e30f, -1e30f};
    float l_lo[2] = {0.0f, 0.0f},     l_hi[2] = {0.0f, 0.0f};

    const int rl = tid >> 3;
    const int cl = (tid & 7) * 8;
    const __half* kb0 = qkv + (size_t)(b * Tn) * rst + Cc + h * HD;
    const __half* vb0 = qkv + (size_t)(b * Tn) * rst + 2 * Cc + h * HD;

    #pragma unroll
    for (int it = 0; it < 4; it++) {
        const int row = rl + it * 16;
        CP16(sbK + (uint32_t)((row * KSTH + cl) * 2), kb0 + (size_t)row * rst + cl);
        CP16(sbV + (uint32_t)((row * VSTH + cl) * 2), vb0 + (size_t)row * rst + cl);
    }
    CP_COMMIT();

    const float SC = 0.125f * 1.4426950408889634f;   // scale * log2(e)
    const int last = 2 * qt + 1;
    int buf = 0;
    for (int kt = 0; kt <= last; kt++) {
        if (kt < last) {
            const int nb = buf ^ 1;
            const __half* kb = kb0 + (size_t)(kt + 1) * 64 * rst;
            const __half* vb = vb0 + (size_t)(kt + 1) * 64 * rst;
            #pragma unroll
            for (int it = 0; it < 4; it++) {
                const int row = rl + it * 16;
                CP16(sbK + (uint32_t)(((nb * 64 + row) * KSTH + cl) * 2),
                     kb + (size_t)row * rst + cl);
                CP16(sbV + (uint32_t)(((nb * 64 + row) * VSTH + cl) * 2),
                     vb + (size_t)row * rst + cl);
            }
            CP_COMMIT();
            CP_WAIT1();
        } else {
            CP_WAIT0();
        }
        __syncthreads();

        const int k0 = kt * 64;
        if (k0 <= q0 + wq0 + 31) {
            const uint32_t kbase = sbK + (uint32_t)(buf * 64 * KSTH * 2);
            const uint32_t vbase = sbV + (uint32_t)(buf * 64 * VSTH * 2);

            float s[2][8][4];
            #pragma unroll
            for (int rg = 0; rg < 2; rg++)
                #pragma unroll
                for (int j = 0; j < 8; j++)
                    #pragma unroll
                    for (int r = 0; r < 4; r++) s[rg][j][r] = 0.0f;

            #pragma unroll
            for (int ks = 0; ks < 4; ks++) {
                #pragma unroll
                for (int jp = 0; jp < 4; jp++) {
                    uint32_t b0, b1, b2, b3;
                    LDMX4(b0, b1, b2, b3,
                          kbase + (uint32_t)((((jp * 16 + krow) * KSTH) +
                                              ks * 16 + kcol) * 2));
                    uint32_t bf0[2] = { b0, b1 }, bf1[2] = { b2, b3 };
                    mma_f16(s[0][2 * jp],     qf[0][ks], bf0);
                    mma_f16(s[0][2 * jp + 1], qf[0][ks], bf1);
                    mma_f16(s[1][2 * jp],     qf[1][ks], bf0);
                    mma_f16(s[1][2 * jp + 1], qf[1][ks], bf1);
                }
            }

            #pragma unroll
            for (int rg = 0; rg < 2; rg++)
                #pragma unroll
                for (int j = 0; j < 8; j++)
                    #pragma unroll
                    for (int r = 0; r < 4; r++) s[rg][j][r] *= SC;

            #pragma unroll
            for (int rg = 0; rg < 2; rg++) {
                const int rb = q0 + wq0 + rg * 16;
                if (k0 + 63 > rb) {
                    const int rlo = rb + gr, rhi = rlo + 8;
                    #pragma unroll
                    for (int j = 0; j < 8; j++) {
                        const int col = k0 + j * 8 + gc * 2;
                        if (col     > rlo) s[rg][j][0] = -1e30f;
                        if (col + 1 > rlo) s[rg][j][1] = -1e30f;
                        if (col     > rhi) s[rg][j][2] = -1e30f;
                        if (col + 1 > rhi) s[rg][j][3] = -1e30f;
                    }
                }

                float mx_lo = -1e30f, mx_hi = -1e30f;
                #pragma unroll
                for (int j = 0; j < 8; j++) {
                    mx_lo = fmaxf(mx_lo, fmaxf(s[rg][j][0], s[rg][j][1]));
                    mx_hi = fmaxf(mx_hi, fmaxf(s[rg][j][2], s[rg][j][3]));
                }
                mx_lo = fmaxf(mx_lo, __shfl_xor_sync(0xffffffffu, mx_lo, 1));
                mx_lo = fmaxf(mx_lo, __shfl_xor_sync(0xffffffffu, mx_lo, 2));
                mx_hi = fmaxf(mx_hi, __shfl_xor_sync(0xffffffffu, mx_hi, 1));
                mx_hi = fmaxf(mx_hi, __shfl_xor_sync(0xffffffffu, mx_hi, 2));

                const float nm_lo = fmaxf(m_lo[rg], mx_lo);
                const float nm_hi = fmaxf(m_hi[rg], mx_hi);
                const float al_lo = exp2f(m_lo[rg] - nm_lo);
                const float al_hi = exp2f(m_hi[rg] - nm_hi);
                m_lo[rg] = nm_lo; m_hi[rg] = nm_hi;

                float sm_lo = 0.0f, sm_hi = 0.0f;
                #pragma unroll
                for (int j = 0; j < 8; j++) {
                    s[rg][j][0] = exp2f(s[rg][j][0] - nm_lo);
                    s[rg][j][1] = exp2f(s[rg][j][1] - nm_lo);
                    s[rg][j][2] = exp2f(s[rg][j][2] - nm_hi);
                    s[rg][j][3] = exp2f(s[rg][j][3] - nm_hi);
                    sm_lo += s[rg][j][0] + s[rg][j][1];
                    sm_hi += s[rg][j][2] + s[rg][j][3];
                }
                sm_lo += __shfl_xor_sync(0xffffffffu, sm_lo, 1);
                sm_lo += __shfl_xor_sync(0xffffffffu, sm_lo, 2);
                sm_hi += __shfl_xor_sync(0xffffffffu, sm_hi, 1);
                sm_hi += __shfl_xor_sync(0xffffffffu, sm_hi, 2);
                l_lo[rg] = l_lo[rg] * al_lo + sm_lo;
                l_hi[rg] = l_hi[rg] * al_hi + sm_hi;

                #pragma unroll
                for (int j = 0; j < 8; j++) {
                    o[rg][j][0] *= al_lo; o[rg][j][1] *= al_lo;
                    o[rg][j][2] *= al_hi; o[rg][j][3] *= al_hi;
                }
            }

            #pragma unroll
            for (int kk = 0; kk < 4; kk++) {
                uint32_t pf0[4], pf1[4];
                pf0[0] = packh2(s[0][2 * kk][0],     s[0][2 * kk][1]);
                pf0[1] = packh2(s[0][2 * kk][2],     s[0][2 * kk][3]);
                pf0[2] = packh2(s[0][2 * kk + 1][0], s[0][2 * kk + 1][1]);
                pf0[3] = packh2(s[0][2 * kk + 1][2], s[0][2 * kk + 1][3]);
                pf1[0] = packh2(s[1][2 * kk][0],     s[1][2 * kk][1]);
                pf1[1] = packh2(s[1][2 * kk][2],     s[1][2 * kk][3]);
                pf1[2] = packh2(s[1][2 * kk + 1][0], s[1][2 * kk + 1][1]);
                pf1[3] = packh2(s[1][2 * kk + 1][2], s[1][2 * kk + 1][3]);
                #pragma unroll
                for (int nb = 0; nb < 4; nb++) {
                    uint32_t b0, b1, b2, b3;
                    LDMX4T(b0, b1, b2, b3,
                           vbase + (uint32_t)((((kk * 16 + vrow) * VSTH) +
                                               nb * 16 + vcol) * 2));
                    uint32_t bf0[2] = { b0, b1 }, bf1[2] = { b2, b3 };
                    mma_f16(o[0][2 * nb],     pf0, bf0);
                    mma_f16(o[0][2 * nb + 1], pf0, bf1);
                    mma_f16(o[1][2 * nb],     pf1, bf0);
                    mma_f16(o[1][2 * nb + 1], pf1, bf1);
                }
            }
        }
        __syncthreads();
        buf ^= 1;
    }

    // ---- normalize + write half ----
    #pragma unroll
    for (int rg = 0; rg < 2; rg++) {
        const float il_lo = 1.0f / l_lo[rg];
        const float il_hi = 1.0f / l_hi[rg];
        __half* olo = outp + (size_t)(b * Tn + q0 + wq0 + rg * 16 + gr) * Cc
                           + h * HD + gc * 2;
        __half* ohi = olo + (size_t)8 * Cc;
        #pragma unroll
        for (int j2 = 0; j2 < 8; j2++) {
            *(__half2*)(olo + j2 * 8) =
                __floats2half2_rn(o[rg][j2][0] * il_lo, o[rg][j2][1] * il_lo);
            *(__half2*)(ohi + j2 * 8) =
                __floats2half2_rn(o[rg][j2][2] * il_hi, o[rg][j2][3] * il_hi);
        }
    }
}

// ===========================================================================
// Launch
// ===========================================================================
extern "C" void kernel_launch(void* const* d_in, const int* in_sizes, int n_in,
                              void* d_out, int out_size)
{
    const float* x      = (const float*)d_in[0];   // (B,T,C)
    const float* w_attn = (const float*)d_in[1];   // (3C, C)
    const float* w_proj = (const float*)d_in[2];   // (C, C)
    float* out = (float*)d_out;                    // (B,T,C)

    __half *xh_p, *wah_p, *wph_p, *qkv_p, *ath_p;
    cudaGetSymbolAddress((void**)&xh_p,  g_xh);
    cudaGetSymbolAddress((void**)&wah_p, g_wah);
    cudaGetSymbolAddress((void**)&wph_p, g_wph);
    cudaGetSymbolAddress((void**)&qkv_p, g_qkv);
    cudaGetSymbolAddress((void**)&ath_p, g_ath);

    cudaFuncSetAttribute(gemm_f16_kernel<0>,
                         cudaFuncAttributeMaxDynamicSharedMemorySize, GEMM_SMEM);
    cudaFuncSetAttribute(gemm_f16_kernel<1>,
                         cudaFuncAttributeMaxDynamicSharedMemorySize, GEMM_SMEM);
    cudaFuncSetAttribute(flash_tc_kernel,
                         cudaFuncAttributeMaxDynamicSharedMemorySize, FLASH_SMEM);

    // 0) convert all inputs to half (single fused launch)
    {
        const int n8x = MTOT * Cc / 8;
        const int n8a = 3 * Cc * Cc / 8;
        const int n8p = Cc * Cc / 8;
        const int tot = n8x + n8a + n8p;
        to_half3_kernel<<<(tot + 255) / 256, 256>>>(
            (const float4*)x,      (uint4*)xh_p,  n8x,
            (const float4*)w_attn, (uint4*)wah_p, n8a,
            (const float4*)w_proj, (uint4*)wph_p, n8p);
    }

    // 1) QKV = x @ w_attn^T : M=8192, N=3072, K=1024 -> half (persistent)
    gemm_f16_kernel<1><<<GEMM_GRID, 128, GEMM_SMEM>>>(
        xh_p, wah_p, nullptr, qkv_p, MTOT, 3 * Cc, Cc);

    // 2) Flash attention -> att half
    {
        dim3 grid(Tn / QROWS, Bn * NH);
        flash_tc_kernel<<<grid, 128, FLASH_SMEM>>>(qkv_p, ath_p);
    }

    // 3) out = att @ w_proj^T : M=8192, N=1024, K=1024 (f32 out, persistent)
    gemm_f16_kernel<0><<<GEMM_GRID, 128, GEMM_SMEM>>>(
        ath_p, wph_p, out, nullptr, MTOT, Cc, Cc);
}

// round 17
// speedup vs baseline: 2.3895x; 1.0218x over previous
#include <cuda_runtime.h>
#include <cuda_fp16.h>
#include <math.h>
#include <stdint.h>

// Problem constants (B=4, T=2048, C=1024, H=16, D=64)
#define Bn   4
#define Tn   2048
#define Cc   1024
#define NH   16
#define HD   64
#define MTOT (Bn * Tn)          // 8192 rows

// Scratch (device globals: allocation is forbidden)
__device__ __half g_xh [(size_t)MTOT * Cc];        // x (half)
__device__ __half g_wah[(size_t)3 * Cc * Cc];      // w_attn (half)
__device__ __half g_wph[(size_t)Cc * Cc];          // w_proj (half)
__device__ __half g_qkv[(size_t)MTOT * 3 * Cc];    // qkv (half), (B*T, 3C)
__device__ __half g_ath[(size_t)MTOT * Cc];        // attention out (half)

// ===========================================================================
// Helpers
// ===========================================================================
__device__ __forceinline__ uint32_t smem_u32(const void* p) {
    uint32_t a;
    asm("{ .reg .u64 t; cvta.to.shared.u64 t, %1; cvt.u32.u64 %0, t; }"
        : "=r"(a) : "l"(p));
    return a;
}
__device__ __forceinline__ uint32_t packh2(float a, float b) {
    __half2 h = __floats2half2_rn(a, b);
    return *(uint32_t*)&h;
}
// fp16 mma: D(16x8,f32) = A(16x16,f16,row) @ B(16x8,f16,col) + D
__device__ __forceinline__ void mma_f16(float* c, const uint32_t* a, const uint32_t* b) {
    asm volatile(
        "mma.sync.aligned.m16n8k16.row.col.f32.f16.f16.f32 "
        "{%0,%1,%2,%3}, {%4,%5,%6,%7}, {%8,%9}, {%0,%1,%2,%3};"
        : "+f"(c[0]), "+f"(c[1]), "+f"(c[2]), "+f"(c[3])
        : "r"(a[0]), "r"(a[1]), "r"(a[2]), "r"(a[3]), "r"(b[0]), "r"(b[1]));
}
// two fp16 exponentials (base 2) in one MUFU op
#define EX2H2(d, a) \
    asm("ex2.approx.f16x2 %0, %1;" : "=r"(d) : "r"(a))
#define LDMX4(r0,r1,r2,r3,addr) \
    asm volatile("ldmatrix.sync.aligned.m8n8.x4.shared.b16 {%0,%1,%2,%3}, [%4];" \
        : "=r"(r0), "=r"(r1), "=r"(r2), "=r"(r3) : "r"(addr))
#define LDMX4T(r0,r1,r2,r3,addr) \
    asm volatile("ldmatrix.sync.aligned.m8n8.x4.trans.shared.b16 {%0,%1,%2,%3}, [%4];" \
        : "=r"(r0), "=r"(r1), "=r"(r2), "=r"(r3) : "r"(addr))
#define CP16(smem, gmem) \
    asm volatile("cp.async.cg.shared.global [%0], [%1], 16;" \
                 :: "r"(smem), "l"(gmem) : "memory")
#define CP_COMMIT() asm volatile("cp.async.commit_group;" ::: "memory")
#define CP_WAIT0()  asm volatile("cp.async.wait_group 0;" ::: "memory")
#define CP_WAIT1()  asm volatile("cp.async.wait_group 1;" ::: "memory")

// ===========================================================================
// Fused convert pass: x, w_attn, w_proj fp32 -> fp16 in ONE launch
// ===========================================================================
__global__ __launch_bounds__(256) void to_half3_kernel(
    const float4* __restrict__ x,  uint4* __restrict__ xh,  int n8x,
    const float4* __restrict__ wa, uint4* __restrict__ wah, int n8a,
    const float4* __restrict__ wp, uint4* __restrict__ wph, int n8p)
{
    int i = blockIdx.x * blockDim.x + threadIdx.x;
    const float4* in;
    uint4* out;
    int idx;
    if (i < n8x)            { in = x;  out = xh;  idx = i; }
    else if (i < n8x + n8a) { in = wa; out = wah; idx = i - n8x; }
    else if (i < n8x + n8a + n8p) { in = wp; out = wph; idx = i - n8x - n8a; }
    else return;
    float4 a = in[2 * idx], b = in[2 * idx + 1];
    uint4 o = { packh2(a.x, a.y), packh2(a.z, a.w),
                packh2(b.x, b.y), packh2(b.z, b.w) };
    out[idx] = o;
}

// ===========================================================================
// FP16 GEMM (PERSISTENT, 3-stage, loads-first): C[M,N] = A[M,K] @ B[N,K]^T.
// (unchanged from R15)
// ===========================================================================
#define GH_ST  72
#define HTILE  (128 * GH_ST)
#define HSTAGE (2 * HTILE)
#define GEMM_SMEM (3 * HSTAGE * 2)            // 110592 B
#define GEMM_GRID 304                         // 2 CTAs/SM x 152 SMs

template <int MODE>
__global__ __launch_bounds__(128, 2) void gemm_f16_kernel(
    const __half* __restrict__ A, const __half* __restrict__ B,
    float* __restrict__ C, __half* __restrict__ HC, int M, int N, int K)
{
    extern __shared__ char smc[];
    const uint32_t sb = smem_u32(smc);
    const int tid = threadIdx.x;
    const int wid = tid >> 5, lane = tid & 31;
    const int gr = lane >> 2, gc = lane & 3;
    const int wm0 = (wid >> 1) * 64, wn0 = (wid & 1) * 64;

    const uint32_t arow = (lane & 7) + ((lane >> 3) & 1) * 8;
    const uint32_t acol = (lane >> 4) * 8;
    const uint32_t brow = (lane & 7) + (lane >> 4) * 8;
    const uint32_t bcol = ((lane >> 3) & 1) * 8;

    const int rl = tid >> 3;
    const int cl = (tid & 7) * 8;

    const int KCH = K / 64;
    const int NX = N / 128;
    const int ntiles = (M / 128) * NX;

    for (int t = blockIdx.x; t < ntiles; t += gridDim.x) {
        const int m0 = (t / NX) * 128, n0 = (t % NX) * 128;

        float acc[4][8][4];
        #pragma unroll
        for (int i = 0; i < 4; i++)
            #pragma unroll
            for (int j = 0; j < 8; j++)
                #pragma unroll
                for (int r = 0; r < 4; r++) acc[i][j][r] = 0.0f;

        const __half* Ag = A + (size_t)(m0 + rl) * K + cl;
        const __half* Bg = B + (size_t)(n0 + rl) * K + cl;

        #pragma unroll
        for (int s = 0; s < 2; s++) {
            const uint32_t st = sb + (uint32_t)(s * HSTAGE * 2);
            #pragma unroll
            for (int it = 0; it < 8; it++) {
                uint32_t off = (uint32_t)(((rl + it * 16) * GH_ST + cl) * 2);
                CP16(st + off,             Ag + (size_t)it * 16 * K + s * 64);
                CP16(st + off + HTILE * 2, Bg + (size_t)it * 16 * K + s * 64);
            }
            CP_COMMIT();
        }

        for (int c = 0; c < KCH; c++) {
            if (c + 1 < KCH) { CP_WAIT1(); } else { CP_WAIT0(); }
            __syncthreads();

            if (c + 2 < KCH) {
                const uint32_t st = sb + (uint32_t)(((c + 2) % 3) * HSTAGE * 2);
                #pragma unroll
                for (int it = 0; it < 8; it++) {
                    uint32_t off = (uint32_t)(((rl + it * 16) * GH_ST + cl) * 2);
                    CP16(st + off,             Ag + (size_t)it * 16 * K + (c + 2) * 64);
                    CP16(st + off + HTILE * 2, Bg + (size_t)it * 16 * K + (c + 2) * 64);
                }
                CP_COMMIT();
            }

            const uint32_t sA = sb + (uint32_t)((c % 3) * HSTAGE * 2);
            const uint32_t sB = sA + (uint32_t)(HTILE * 2);
            #pragma unroll
            for (int ks = 0; ks < 4; ks++) {
                uint32_t af[4][4], bf[8][2];
                #pragma unroll
                for (int i = 0; i < 4; i++)
                    LDMX4(af[i][0], af[i][1], af[i][2], af[i][3],
                          sA + (uint32_t)((((wm0 + i * 16 + arow) * GH_ST) +
                                           ks * 16 + acol) * 2));
                #pragma unroll
                for (int jp = 0; jp < 4; jp++) {
                    uint32_t b0, b1, b2, b3;
                    LDMX4(b0, b1, b2, b3,
                          sB + (uint32_t)((((wn0 + jp * 16 + brow) * GH_ST) +
                                           ks * 16 + bcol) * 2));
                    bf[2 * jp][0] = b0; bf[2 * jp][1] = b1;
                    bf[2 * jp + 1][0] = b2; bf[2 * jp + 1][1] = b3;
                }
                #pragma unroll
                for (int i = 0; i < 4; i++)
                    #pragma unroll
                    for (int j = 0; j < 8; j++)
                        mma_f16(acc[i][j], af[i], bf[j]);
            }
        }
        __syncthreads();

        #pragma unroll
        for (int i = 0; i < 4; i++)
            #pragma unroll
            for (int j = 0; j < 8; j++) {
                const int row = m0 + wm0 + i * 16 + gr;
                const int col = n0 + wn0 + j * 8 + gc * 2;
                if (MODE == 0) {
                    float* cr = C + (size_t)row * N + col;
                    float2 v0 = { acc[i][j][0], acc[i][j][1] };
                    float2 v1 = { acc[i][j][2], acc[i][j][3] };
                    *(float2*)cr           = v0;
                    *(float2*)(cr + 8 * N) = v1;
                } else {
                    __half* hr = HC + (size_t)row * N + col;
                    *(__half2*)hr                   = __floats2half2_rn(acc[i][j][0], acc[i][j][1]);
                    *(__half2*)(hr + (size_t)8 * N) = __floats2half2_rn(acc[i][j][2], acc[i][j][3]);
                }
            }
    }
}

// ===========================================================================
// Flash attention (causal), all-fp16 mma. Softmax restructured:
// raw-domain max; exp via ONE FFMA (s*SC - nm*SC) + f16x2 pack + ex2.f16x2;
// ex2 outputs ARE the P A-fragments; row sums via __hadd2 tree.
// ===========================================================================
#define KSTH 72
#define VSTH 72
#define QROWS 128
#define FLASH_SMEM ((2 * 64 * KSTH + 2 * 64 * VSTH) * 2)   // 36864 B

__global__ __launch_bounds__(128, 2) void flash_tc_kernel(
    const __half* __restrict__ qkv, __half* __restrict__ outp)
{
    extern __shared__ char smc[];
    __half* Ksm = (__half*)smc;                   // [2][64*KSTH]
    __half* Vsm = Ksm + 2 * 64 * KSTH;            // [2][64*VSTH]
    const uint32_t sbK = smem_u32(Ksm);
    const uint32_t sbV = smem_u32(Vsm);

    const int tid = threadIdx.x;
    const int wid = tid >> 5, lane = tid & 31;
    const int gr = lane >> 2, gc = lane & 3;
    const int qt = gridDim.x - 1 - blockIdx.x;    // heavy tiles first
    const int b  = blockIdx.y >> 4;
    const int h  = blockIdx.y & 15;
    const int q0 = qt * QROWS;
    const int wq0 = wid * 32;
    const size_t rst = 3 * Cc;

    const uint32_t krow = (lane & 7) + (lane >> 4) * 8;
    const uint32_t kcol = ((lane >> 3) & 1) * 8;
    const uint32_t vrow = lane & 15;
    const uint32_t vcol = (lane >> 4) * 8;

    // ---- Q fragments ----
    uint32_t qf[2][4][4];
    #pragma unroll
    for (int rg = 0; rg < 2; rg++) {
        const __half* qlo = qkv + (size_t)(b * Tn + q0 + wq0 + rg * 16 + gr) * rst
                                + h * HD;
        const __half* qhi = qlo + 8 * rst;
        #pragma unroll
        for (int ks = 0; ks < 4; ks++) {
            qf[rg][ks][0] = *(const uint32_t*)(qlo + ks * 16 + gc * 2);
            qf[rg][ks][1] = *(const uint32_t*)(qhi + ks * 16 + gc * 2);
            qf[rg][ks][2] = *(const uint32_t*)(qlo + ks * 16 + gc * 2 + 8);
            qf[rg][ks][3] = *(const uint32_t*)(qhi + ks * 16 + gc * 2 + 8);
        }
    }

    float o[2][8][4];
    #pragma unroll
    for (int rg = 0; rg < 2; rg++)
        #pragma unroll
        for (int j = 0; j < 8; j++)
            #pragma unroll
            for (int r = 0; r < 4; r++) o[rg][j][r] = 0.0f;
    // m: RAW-domain running max; l: f32 running denominators
    float m_lo[2] = {-1e30f, -1e30f}, m_hi[2] = {-1e30f, -1e30f};
    float l_lo[2] = {0.0f, 0.0f},     l_hi[2] = {0.0f, 0.0f};

    const int rl = tid >> 3;
    const int cl = (tid & 7) * 8;
    const __half* kb0 = qkv + (size_t)(b * Tn) * rst + Cc + h * HD;
    const __half* vb0 = qkv + (size_t)(b * Tn) * rst + 2 * Cc + h * HD;

    #pragma unroll
    for (int it = 0; it < 4; it++) {
        const int row = rl + it * 16;
        CP16(sbK + (uint32_t)((row * KSTH + cl) * 2), kb0 + (size_t)row * rst + cl);
        CP16(sbV + (uint32_t)((row * VSTH + cl) * 2), vb0 + (size_t)row * rst + cl);
    }
    CP_COMMIT();

    const float SC = 0.125f * 1.4426950408889634f;   // scale * log2(e)
    const int last = 2 * qt + 1;
    int buf = 0;
    for (int kt = 0; kt <= last; kt++) {
        if (kt < last) {
            const int nb = buf ^ 1;
            const __half* kb = kb0 + (size_t)(kt + 1) * 64 * rst;
            const __half* vb = vb0 + (size_t)(kt + 1) * 64 * rst;
            #pragma unroll
            for (int it = 0; it < 4; it++) {
                const int row = rl + it * 16;
                CP16(sbK + (uint32_t)(((nb * 64 + row) * KSTH + cl) * 2),
                     kb + (size_t)row * rst + cl);
                CP16(sbV + (uint32_t)(((nb * 64 + row) * VSTH + cl) * 2),
                     vb + (size_t)row * rst + cl);
            }
            CP_COMMIT();
            CP_WAIT1();
        } else {
            CP_WAIT0();
        }
        __syncthreads();

        const int k0 = kt * 64;
        if (k0 <= q0 + wq0 + 31) {
            const uint32_t kbase = sbK + (uint32_t)(buf * 64 * KSTH * 2);
            const uint32_t vbase = sbV + (uint32_t)(buf * 64 * VSTH * 2);

            // ---- S = Q@K^T (raw scores, f32) ----
            float s[2][8][4];
            #pragma unroll
            for (int rg = 0; rg < 2; rg++)
                #pragma unroll
                for (int j = 0; j < 8; j++)
                    #pragma unroll
                    for (int r = 0; r < 4; r++) s[rg][j][r] = 0.0f;

            #pragma unroll
            for (int ks = 0; ks < 4; ks++) {
                #pragma unroll
                for (int jp = 0; jp < 4; jp++) {
                    uint32_t b0, b1, b2, b3;
                    LDMX4(b0, b1, b2, b3,
                          kbase + (uint32_t)((((jp * 16 + krow) * KSTH) +
                                              ks * 16 + kcol) * 2));
                    uint32_t bf0[2] = { b0, b1 }, bf1[2] = { b2, b3 };
                    mma_f16(s[0][2 * jp],     qf[0][ks], bf0);
                    mma_f16(s[0][2 * jp + 1], qf[0][ks], bf1);
                    mma_f16(s[1][2 * jp],     qf[1][ks], bf0);
                    mma_f16(s[1][2 * jp + 1], qf[1][ks], bf1);
                }
            }

            // P fragments (f16x2): [rg][lo/hi row][j]
            uint32_t pfr[2][2][8];

            #pragma unroll
            for (int rg = 0; rg < 2; rg++) {
                const int rb = q0 + wq0 + rg * 16;
                // causal mask (raw domain)
                if (k0 + 63 > rb) {
                    const int rlo = rb + gr, rhi = rlo + 8;
                    #pragma unroll
                    for (int j = 0; j < 8; j++) {
                        const int col = k0 + j * 8 + gc * 2;
                        if (col     > rlo) s[rg][j][0] = -1e30f;
                        if (col + 1 > rlo) s[rg][j][1] = -1e30f;
                        if (col     > rhi) s[rg][j][2] = -1e30f;
                        if (col + 1 > rhi) s[rg][j][3] = -1e30f;
                    }
                }

                // row max (raw domain)
                float mx_lo = -1e30f, mx_hi = -1e30f;
                #pragma unroll
                for (int j = 0; j < 8; j++) {
                    mx_lo = fmaxf(mx_lo, fmaxf(s[rg][j][0], s[rg][j][1]));
                    mx_hi = fmaxf(mx_hi, fmaxf(s[rg][j][2], s[rg][j][3]));
                }
                mx_lo = fmaxf(mx_lo, __shfl_xor_sync(0xffffffffu, mx_lo, 1));
                mx_lo = fmaxf(mx_lo, __shfl_xor_sync(0xffffffffu, mx_lo, 2));
                mx_hi = fmaxf(mx_hi, __shfl_xor_sync(0xffffffffu, mx_hi, 1));
                mx_hi = fmaxf(mx_hi, __shfl_xor_sync(0xffffffffu, mx_hi, 2));

                const float nm_lo = fmaxf(m_lo[rg], mx_lo);
                const float nm_hi = fmaxf(m_hi[rg], mx_hi);
                const float al_lo = exp2f((m_lo[rg] - nm_lo) * SC);
                const float al_hi = exp2f((m_hi[rg] - nm_hi) * SC);
                m_lo[rg] = nm_lo; m_hi[rg] = nm_hi;
                const float nsc_lo = -nm_lo * SC;
                const float nsc_hi = -nm_hi * SC;

                // exp: t = s*SC - nm*SC (FFMA), pack f16x2, ex2.f16x2
                #pragma unroll
                for (int j = 0; j < 8; j++) {
                    float t0 = fmaf(s[rg][j][0], SC, nsc_lo);
                    float t1 = fmaf(s[rg][j][1], SC, nsc_lo);
                    float t2 = fmaf(s[rg][j][2], SC, nsc_hi);
                    float t3 = fmaf(s[rg][j][3], SC, nsc_hi);
                    uint32_t ulo = packh2(t0, t1);
                    uint32_t uhi = packh2(t2, t3);
                    EX2H2(pfr[rg][0][j], ulo);
                    EX2H2(pfr[rg][1][j], uhi);
                }

                // row sums via __hadd2 tree (f16), finish in f32
                __half2 slo = *(__half2*)&pfr[rg][0][0];
                __half2 shi = *(__half2*)&pfr[rg][1][0];
                #pragma unroll
                for (int j = 1; j < 8; j++) {
                    slo = __hadd2(slo, *(__half2*)&pfr[rg][0][j]);
                    shi = __hadd2(shi, *(__half2*)&pfr[rg][1][j]);
                }
                float2 flo = __half22float2(slo);
                float2 fhi = __half22float2(shi);
                float sm_lo = flo.x + flo.y;
                float sm_hi = fhi.x + fhi.y;
                sm_lo += __shfl_xor_sync(0xffffffffu, sm_lo, 1);
                sm_lo += __shfl_xor_sync(0xffffffffu, sm_lo, 2);
                sm_hi += __shfl_xor_sync(0xffffffffu, sm_hi, 1);
                sm_hi += __shfl_xor_sync(0xffffffffu, sm_hi, 2);
                l_lo[rg] = l_lo[rg] * al_lo + sm_lo;
                l_hi[rg] = l_hi[rg] * al_hi + sm_hi;

                #pragma unroll
                for (int j = 0; j < 8; j++) {
                    o[rg][j][0] *= al_lo; o[rg][j][1] *= al_lo;
                    o[rg][j][2] *= al_hi; o[rg][j][3] *= al_hi;
                }
            }

            // ---- O += P @ V : pfr ARE the A-fragments ----
            #pragma unroll
            for (int kk = 0; kk < 4; kk++) {
                uint32_t pf0[4] = { pfr[0][0][2 * kk], pfr[0][1][2 * kk],
                                    pfr[0][0][2 * kk + 1], pfr[0][1][2 * kk + 1] };
                uint32_t pf1[4] = { pfr[1][0][2 * kk], pfr[1][1][2 * kk],
                                    pfr[1][0][2 * kk + 1], pfr[1][1][2 * kk + 1] };
                #pragma unroll
                for (int nb = 0; nb < 4; nb++) {
                    uint32_t b0, b1, b2, b3;
                    LDMX4T(b0, b1, b2, b3,
                           vbase + (uint32_t)((((kk * 16 + vrow) * VSTH) +
                                               nb * 16 + vcol) * 2));
                    uint32_t bf0[2] = { b0, b1 }, bf1[2] = { b2, b3 };
                    mma_f16(o[0][2 * nb],     pf0, bf0);
                    mma_f16(o[0][2 * nb + 1], pf0, bf1);
                    mma_f16(o[1][2 * nb],     pf1, bf0);
                    mma_f16(o[1][2 * nb + 1], pf1, bf1);
                }
            }
        }
        __syncthreads();
        buf ^= 1;
    }

    // ---- normalize + write half ----
    #pragma unroll
    for (int rg = 0; rg < 2; rg++) {
        const float il_lo = 1.0f / l_lo[rg];
        const float il_hi = 1.0f / l_hi[rg];
        __half* olo = outp + (size_t)(b * Tn + q0 + wq0 + rg * 16 + gr) * Cc
                           + h * HD + gc * 2;
        __half* ohi = olo + (size_t)8 * Cc;
        #pragma unroll
        for (int j2 = 0; j2 < 8; j2++) {
            *(__half2*)(olo + j2 * 8) =
                __floats2half2_rn(o[rg][j2][0] * il_lo, o[rg][j2][1] * il_lo);
            *(__half2*)(ohi + j2 * 8) =
                __floats2half2_rn(o[rg][j2][2] * il_hi, o[rg][j2][3] * il_hi);
        }
    }
}

// ===========================================================================
// Launch
// ===========================================================================
extern "C" void kernel_launch(void* const* d_in, const int* in_sizes, int n_in,
                              void* d_out, int out_size)
{
    const float* x      = (const float*)d_in[0];   // (B,T,C)
    const float* w_attn = (const float*)d_in[1];   // (3C, C)
    const float* w_proj = (const float*)d_in[2];   // (C, C)
    float* out = (float*)d_out;                    // (B,T,C)

    __half *xh_p, *wah_p, *wph_p, *qkv_p, *ath_p;
    cudaGetSymbolAddress((void**)&xh_p,  g_xh);
    cudaGetSymbolAddress((void**)&wah_p, g_wah);
    cudaGetSymbolAddress((void**)&wph_p, g_wph);
    cudaGetSymbolAddress((void**)&qkv_p, g_qkv);
    cudaGetSymbolAddress((void**)&ath_p, g_ath);

    cudaFuncSetAttribute(gemm_f16_kernel<0>,
                         cudaFuncAttributeMaxDynamicSharedMemorySize, GEMM_SMEM);
    cudaFuncSetAttribute(gemm_f16_kernel<1>,
                         cudaFuncAttributeMaxDynamicSharedMemorySize, GEMM_SMEM);
    cudaFuncSetAttribute(flash_tc_kernel,
                         cudaFuncAttributeMaxDynamicSharedMemorySize, FLASH_SMEM);

    // 0) convert all inputs to half (single fused launch)
    {
        const int n8x = MTOT * Cc / 8;
        const int n8a = 3 * Cc * Cc / 8;
        const int n8p = Cc * Cc / 8;
        const int tot = n8x + n8a + n8p;
        to_half3_kernel<<<(tot + 255) / 256, 256>>>(
            (const float4*)x,      (uint4*)xh_p,  n8x,
            (const float4*)w_attn, (uint4*)wah_p, n8a,
            (const float4*)w_proj, (uint4*)wph_p, n8p);
    }

    // 1) QKV = x @ w_attn^T : M=8192, N=3072, K=1024 -> half (persistent)
    gemm_f16_kernel<1><<<GEMM_GRID, 128, GEMM_SMEM>>>(
        xh_p, wah_p, nullptr, qkv_p, MTOT, 3 * Cc, Cc);

    // 2) Flash attention -> att half
    {
        dim3 grid(Tn / QROWS, Bn * NH);
        flash_tc_kernel<<<grid, 128, FLASH_SMEM>>>(qkv_p, ath_p);
    }

    // 3) out = att @ w_proj^T : M=8192, N=1024, K=1024 (f32 out, persistent)
    gemm_f16_kernel<0><<<GEMM_GRID, 128, GEMM_SMEM>>>(
        ath_p, wph_p, out, nullptr, MTOT, Cc, Cc);
}